// round 4
// baseline (speedup 1.0000x reference)
#include <cuda_runtime.h>
#include <math.h>

#define BB 16
#define NN 1024
#define HD 128
#define NEGV (-9000000000000000.0f)
#define ALPHAV 0.2f

// ---------------- scratch (device globals; no allocation allowed) ----------------
__device__ float g_Y [BB*NN*HD];
__device__ float g_X1[BB*NN*HD];
__device__ float g_X2[BB*NN*HD];
__device__ float g_Wh[BB*NN*HD];
__device__ float g_x3[BB*NN*HD];
__device__ float g_s1[BB*NN];
__device__ float g_s2[BB*NN];
__device__ float g_satt[BB*NN];
__device__ float g_psum[BB*16*HD];
__device__ float g_pmax[BB*16*HD];

// ---------------- PTX helpers ----------------
__device__ __forceinline__ unsigned smem_u32(const void* p) {
    return (unsigned)__cvta_generic_to_shared(p);
}
__device__ __forceinline__ void cpa16(void* s, const void* g) {
    asm volatile("cp.async.cg.shared.global [%0], [%1], 16;" :: "r"(smem_u32(s)), "l"(g));
}
__device__ __forceinline__ void cpa_commit() { asm volatile("cp.async.commit_group;"); }
template<int N>
__device__ __forceinline__ void cpa_wait() { asm volatile("cp.async.wait_group %0;" :: "n"(N)); }
__device__ __forceinline__ unsigned f2tf(float f) {
    unsigned u; asm("cvt.rna.tf32.f32 %0, %1;" : "=r"(u) : "f"(f)); return u;
}
__device__ __forceinline__ void mma_tf32(float* c, const unsigned* a, const unsigned* b) {
    asm volatile(
        "mma.sync.aligned.m16n8k8.row.col.f32.tf32.tf32.f32 "
        "{%0,%1,%2,%3}, {%4,%5,%6,%7}, {%8,%9}, {%0,%1,%2,%3};"
        : "+f"(c[0]), "+f"(c[1]), "+f"(c[2]), "+f"(c[3])
        : "r"(a[0]), "r"(a[1]), "r"(a[2]), "r"(a[3]), "r"(b[0]), "r"(b[1]));
}

// ============================================================================
// Feature GEMM (fp32 SIMT): C = X @ W, outputs pre-rounded to tf32.
// ============================================================================
template<int SRC, int DST>
__global__ __launch_bounds__(256) void feat_gemm(const float* __restrict__ Xext,
                                                 const float* __restrict__ W) {
    const float* X = (SRC == 0) ? Xext : (SRC == 1) ? (const float*)g_X1 : (const float*)g_X2;
    float* C = (DST == 0) ? (float*)g_Y : (float*)g_Wh;

    __shared__ float As[64][32];
    __shared__ float Bs[32][128];
    const int r0 = blockIdx.x * 64;
    const int rg = threadIdx.x >> 5;
    const int cg = threadIdx.x & 31;
    float acc[8][4] = {};

    for (int k0 = 0; k0 < 128; k0 += 32) {
        #pragma unroll
        for (int i = threadIdx.x; i < 512; i += 256) {
            int r = i >> 3, q = i & 7;
            *(float4*)&As[r][q*4] = *(const float4*)&X[(size_t)(r0 + r)*128 + k0 + q*4];
        }
        #pragma unroll
        for (int i = threadIdx.x; i < 1024; i += 256) {
            int r = i >> 5, q = i & 31;
            *(float4*)&Bs[r][q*4] = *(const float4*)&W[(k0 + r)*128 + q*4];
        }
        __syncthreads();
        #pragma unroll
        for (int kk = 0; kk < 32; kk++) {
            float4 bv = *(float4*)&Bs[kk][cg*4];
            #pragma unroll
            for (int r = 0; r < 8; r++) {
                float a = As[rg*8 + r][kk];
                acc[r][0] += a * bv.x; acc[r][1] += a * bv.y;
                acc[r][2] += a * bv.z; acc[r][3] += a * bv.w;
            }
        }
        __syncthreads();
    }
    #pragma unroll
    for (int r = 0; r < 8; r++) {
        float4 v;
        v.x = __uint_as_float(f2tf(acc[r][0]));
        v.y = __uint_as_float(f2tf(acc[r][1]));
        v.z = __uint_as_float(f2tf(acc[r][2]));
        v.w = __uint_as_float(f2tf(acc[r][3]));
        *(float4*)&C[(size_t)(r0 + rg*8 + r)*128 + cg*4] = v;
    }
}

// ============================================================================
// Adjacency GEMM v3 (tf32 tensor cores):
//   CTA tile 128x128, 8 warps (4m x 2n), warp tile 32x64.
//   3-stage cp.async pipeline, ONE __syncthreads per k-tile
//   (next stage's load is issued after compute; the target buffer's last
//    reader finished before this iteration's barrier).
// ============================================================================
#define ADJ_A_BYTES (128*36*4)
#define ADJ_B_BYTES (32*136*4)
#define ADJ_SMEM_BYTES (3*(ADJ_A_BYTES + ADJ_B_BYTES))   // 107520

template<int MODE>
__global__ __launch_bounds__(256, 1) void adj_gemm_tc(const float* __restrict__ adj,
                                                      const float* __restrict__ mask) {
    extern __shared__ char dynsm[];
    float (*As)[128][36] = reinterpret_cast<float(*)[128][36]>(dynsm);
    float (*Bs)[32][136] = reinterpret_cast<float(*)[32][136]>(dynsm + 3*ADJ_A_BYTES);

    const int b  = blockIdx.y;
    const int r0 = blockIdx.x * 128;
    const float* A  = adj + (size_t)b*NN*NN;
    const float* Yb = (const float*)g_Y + (size_t)b*NN*HD;
    const int tid = threadIdx.x;

    auto load_stage = [&](int st, int k0) {
        #pragma unroll
        for (int i = tid; i < 1024; i += 256) {
            int r = i >> 3, q = i & 7;
            cpa16(&As[st][r][q*4], &A[(size_t)(r0 + r)*NN + k0 + q*4]);
        }
        #pragma unroll
        for (int i = tid; i < 1024; i += 256) {
            int r = i >> 5, q = i & 31;
            cpa16(&Bs[st][r][q*4], &Yb[(size_t)(k0 + r)*HD + q*4]);
        }
        cpa_commit();
    };

    load_stage(0, 0);
    load_stage(1, 32);

    const int warp = tid >> 5, lane = tid & 31;
    const int wr = (warp >> 1) * 32;     // 0,32,64,96
    const int wc = (warp & 1) * 64;      // 0,64
    const int lr = lane >> 2;            // 0..7
    const int lc = lane & 3;             // 0..3

    float acc[2][8][4];
    #pragma unroll
    for (int mt = 0; mt < 2; mt++)
        #pragma unroll
        for (int n = 0; n < 8; n++)
            #pragma unroll
            for (int q = 0; q < 4; q++) acc[mt][n][q] = 0.f;

    for (int kt = 0; kt < 32; kt++) {
        const int cur = kt % 3;
        cpa_wait<1>();
        __syncthreads();

        #pragma unroll
        for (int ks = 0; ks < 32; ks += 8) {
            unsigned af[2][4];
            #pragma unroll
            for (int mt = 0; mt < 2; mt++) {
                int r = wr + mt*16 + lr;
                af[mt][0] = f2tf(As[cur][r    ][ks + lc    ]);
                af[mt][1] = f2tf(As[cur][r + 8][ks + lc    ]);
                af[mt][2] = f2tf(As[cur][r    ][ks + lc + 4]);
                af[mt][3] = f2tf(As[cur][r + 8][ks + lc + 4]);
            }
            unsigned bf[8][2];
            #pragma unroll
            for (int n = 0; n < 8; n++) {
                int c = wc + n*8 + lr;
                bf[n][0] = __float_as_uint(Bs[cur][ks + lc    ][c]);   // pre-rounded tf32
                bf[n][1] = __float_as_uint(Bs[cur][ks + lc + 4][c]);
            }
            #pragma unroll
            for (int mt = 0; mt < 2; mt++)
                #pragma unroll
                for (int n = 0; n < 8; n++)
                    mma_tf32(acc[mt][n], af[mt], bf[n]);
        }

        if (kt + 2 < 32) load_stage((kt + 2) % 3, (kt + 2) * 32);
    }

    #pragma unroll
    for (int mt = 0; mt < 2; mt++) {
        #pragma unroll
        for (int half = 0; half < 2; half++) {
            int row = r0 + wr + mt*16 + lr + half*8;
            float mk = mask[b*NN + row];
            size_t base = (size_t)b*NN*HD + (size_t)row*HD;
            #pragma unroll
            for (int n = 0; n < 8; n++) {
                int col = wc + n*8 + 2*lc;
                float v0 = fmaxf(acc[mt][n][half*2 + 0], 0.f) * mk;
                float v1 = fmaxf(acc[mt][n][half*2 + 1], 0.f) * mk;
                if (MODE == 1) {
                    float2 x = *(const float2*)&g_X1[base + col];
                    v0 += x.x; v1 += x.y;
                    *(float2*)&g_X2[base + col] = make_float2(v0, v1);
                } else {
                    *(float2*)&g_X1[base + col] = make_float2(v0, v1);
                }
            }
        }
    }
}

// ============================================================================
// s1/s2 per-row dots
// ============================================================================
__global__ __launch_bounds__(256) void s12_kernel(const float* __restrict__ a) {
    int row  = blockIdx.x * 8 + (threadIdx.x >> 5);
    int lane = threadIdx.x & 31;
    float4 x  = *(const float4*)&g_Wh[(size_t)row*128 + lane*4];
    float4 a1 = *(const float4*)&a[lane*4];
    float4 a2 = *(const float4*)&a[128 + lane*4];
    float d1 = x.x*a1.x + x.y*a1.y + x.z*a1.z + x.w*a1.w;
    float d2 = x.x*a2.x + x.y*a2.y + x.z*a2.z + x.w*a2.w;
    #pragma unroll
    for (int off = 16; off > 0; off >>= 1) {
        d1 += __shfl_xor_sync(0xffffffffu, d1, off);
        d2 += __shfl_xor_sync(0xffffffffu, d2, off);
    }
    if (lane == 0) { g_s1[row] = d1; g_s2[row] = d2; }
}

// ============================================================================
// GAT v2: 128 query rows per CTA, online softmax (2 threads/row x 16 cols),
// P@Wh with warp tile 32x64 (4m x 2n warps).
// ============================================================================
#define GAT_WHS_BYTES (2*32*136*4)            // 34816
#define GAT_PS_BYTES  (128*36*4)              // 18432
#define GAT_SMEM_BYTES (GAT_WHS_BYTES + GAT_PS_BYTES + 4*128*4)

__global__ __launch_bounds__(256, 1) void gat_tc(const float* __restrict__ adj,
                                                 const float* __restrict__ mask) {
    extern __shared__ char dynsm[];
    float (*Whs)[32][136] = reinterpret_cast<float(*)[32][136]>(dynsm);
    float (*Ps)[36]       = reinterpret_cast<float(*)[36]>(dynsm + GAT_WHS_BYTES);
    float* scaleS = reinterpret_cast<float*>(dynsm + GAT_WHS_BYTES + GAT_PS_BYTES);
    float* lS     = scaleS + 128;
    float* s1S    = scaleS + 256;
    float* nmiS   = scaleS + 384;

    const int b  = blockIdx.y;
    const int i0 = blockIdx.x * 128;
    const float* Ab  = adj + (size_t)b*NN*NN;
    const float* Whb = (const float*)g_Wh + (size_t)b*NN*HD;

    const int tid  = threadIdx.x;
    const int warp = tid >> 5, lane = tid & 31;
    const int wr   = (warp >> 1) * 32;
    const int wc   = (warp & 1) * 64;
    const int lr   = lane >> 2, lc = lane & 3;
    const int prow = tid >> 1, psub = tid & 1;

    if (tid < 128) {
        s1S[tid]  = g_s1[b*NN + i0 + tid];
        nmiS[tid] = mask[b*NN + i0 + tid];
    }

    auto load_wh = [&](int st, int j0) {
        #pragma unroll
        for (int i = tid; i < 1024; i += 256) {
            int r = i >> 5, q = i & 31;
            cpa16(&Whs[st][r][q*4], &Whb[(size_t)(j0 + r)*HD + q*4]);
        }
        cpa_commit();
    };

    load_wh(0, 0);

    const float* arow_base = Ab + (size_t)(i0 + prow)*NN + psub*16;
    float4 pa[4];
    #pragma unroll
    for (int q = 0; q < 4; q++) pa[q] = *(const float4*)&arow_base[q*4];

    float acc[2][8][4];
    #pragma unroll
    for (int mt = 0; mt < 2; mt++)
        #pragma unroll
        for (int n = 0; n < 8; n++)
            #pragma unroll
            for (int q = 0; q < 4; q++) acc[mt][n][q] = 0.f;

    float m = -INFINITY, l = 0.f;
    __syncthreads();

    for (int jt = 0; jt < 32; jt++) {
        const int cur = jt & 1;
        const int j0  = jt * 32;
        if (jt + 1 < 32) load_wh(cur ^ 1, j0 + 32);

        // ---- softmax phase: 2 threads/row, 16 cols each ----
        float s1v = s1S[prow], nmi = nmiS[prow];
        float vals[16];
        float tmax = -INFINITY;
        #pragma unroll
        for (int q = 0; q < 4; q++) {
            float4 s2q = *(const float4*)&g_s2[b*NN + j0 + psub*16 + q*4];
            float4 nmq = *(const float4*)&mask[b*NN + j0 + psub*16 + q*4];
            float s2a[4] = {s2q.x, s2q.y, s2q.z, s2q.w};
            float nma[4] = {nmq.x, nmq.y, nmq.z, nmq.w};
            float ava[4] = {pa[q].x, pa[q].y, pa[q].z, pa[q].w};
            #pragma unroll
            for (int jj = 0; jj < 4; jj++) {
                float e = s1v + s2a[jj];
                e = (e > 0.f) ? e : ALPHAV * e;
                float edge = (ava[jj] > 0.f) ? (nma[jj] * nmi) : 0.f;
                float v = (edge > 0.f) ? e : NEGV;
                vals[q*4 + jj] = v;
                tmax = fmaxf(tmax, v);
            }
        }
        tmax = fmaxf(tmax, __shfl_xor_sync(0xffffffffu, tmax, 1));
        float mn    = fmaxf(m, tmax);
        float scale = __expf(m - mn);
        float psum = 0.f;
        #pragma unroll
        for (int jj = 0; jj < 16; jj++) {
            float p = __expf(vals[jj] - mn);
            float pr = __uint_as_float(f2tf(p));   // rounded once; used in BOTH l and P@Wh
            Ps[prow][psub*16 + jj] = pr;
            psum += pr;
        }
        psum += __shfl_xor_sync(0xffffffffu, psum, 1);
        l = l * scale + psum;
        m = mn;
        if (psub == 0) scaleS[prow] = scale;

        if (jt + 1 < 32) {
            #pragma unroll
            for (int q = 0; q < 4; q++) pa[q] = *(const float4*)&arow_base[j0 + 32 + q*4];
        }

        if (jt + 1 < 32) cpa_wait<1>(); else cpa_wait<0>();
        __syncthreads();

        // ---- rescale + P @ Wh (tensor cores, zero cvt) ----
        #pragma unroll
        for (int mt = 0; mt < 2; mt++) {
            float sc0 = scaleS[wr + mt*16 + lr];
            float sc1 = scaleS[wr + mt*16 + lr + 8];
            #pragma unroll
            for (int n = 0; n < 8; n++) {
                acc[mt][n][0] *= sc0; acc[mt][n][1] *= sc0;
                acc[mt][n][2] *= sc1; acc[mt][n][3] *= sc1;
            }
        }
        #pragma unroll
        for (int ks = 0; ks < 32; ks += 8) {
            unsigned af[2][4];
            #pragma unroll
            for (int mt = 0; mt < 2; mt++) {
                int r = wr + mt*16 + lr;
                af[mt][0] = __float_as_uint(Ps[r    ][ks + lc    ]);
                af[mt][1] = __float_as_uint(Ps[r + 8][ks + lc    ]);
                af[mt][2] = __float_as_uint(Ps[r    ][ks + lc + 4]);
                af[mt][3] = __float_as_uint(Ps[r + 8][ks + lc + 4]);
            }
            unsigned bf[8][2];
            #pragma unroll
            for (int n = 0; n < 8; n++) {
                int c = wc + n*8 + lr;
                bf[n][0] = __float_as_uint(Whs[cur][ks + lc    ][c]);
                bf[n][1] = __float_as_uint(Whs[cur][ks + lc + 4][c]);
            }
            #pragma unroll
            for (int mt = 0; mt < 2; mt++)
                #pragma unroll
                for (int n = 0; n < 8; n++)
                    mma_tf32(acc[mt][n], af[mt], bf[n]);
        }
        __syncthreads();
    }

    if (psub == 0) lS[prow] = l;
    __syncthreads();

    float* x3b = (float*)g_x3 + (size_t)b*NN*HD;
    #pragma unroll
    for (int mt = 0; mt < 2; mt++) {
        #pragma unroll
        for (int half = 0; half < 2; half++) {
            int rloc = wr + mt*16 + lr + half*8;
            float inv = 1.f / lS[rloc];
            float nmi = nmiS[rloc];
            size_t base = (size_t)(i0 + rloc)*HD;
            #pragma unroll
            for (int n = 0; n < 8; n++) {
                int col = wc + n*8 + 2*lc;
                float v0 = fmaxf(acc[mt][n][half*2 + 0]*inv, 0.f) * nmi;
                float v1 = fmaxf(acc[mt][n][half*2 + 1]*inv, 0.f) * nmi;
                *(float2*)&x3b[base + col] = make_float2(v0, v1);
            }
        }
    }
}

// ============================================================================
// soft attention sigmoid
// ============================================================================
__global__ __launch_bounds__(256) void satt_kernel(const float* __restrict__ w_sa,
                                                   const float* __restrict__ b_sa) {
    int row  = blockIdx.x * 8 + (threadIdx.x >> 5);
    int lane = threadIdx.x & 31;
    float4 x = *(const float4*)&g_x3[(size_t)row*128 + lane*4];
    float4 w = *(const float4*)&w_sa[lane*4];
    float d = x.x*w.x + x.y*w.y + x.z*w.z + x.w*w.w;
    #pragma unroll
    for (int off = 16; off > 0; off >>= 1)
        d += __shfl_xor_sync(0xffffffffu, d, off);
    if (lane == 0) {
        float z = d + b_sa[0];
        g_satt[row] = 1.f / (1.f + __expf(-z));
    }
}

// ============================================================================
// Final layer + per-tile partial sum/max
// ============================================================================
__global__ __launch_bounds__(256) void final_gemm(const float* __restrict__ Wln,
                                                  const float* __restrict__ bln,
                                                  const float* __restrict__ mask) {
    __shared__ float As[64][32];
    __shared__ float Bs[32][128];
    __shared__ float redS[8][128];
    __shared__ float redM[8][128];
    const int r0 = blockIdx.x * 64;
    const int rg = threadIdx.x >> 5;
    const int cg = threadIdx.x & 31;
    float acc[8][4] = {};

    for (int k0 = 0; k0 < 128; k0 += 32) {
        #pragma unroll
        for (int i = threadIdx.x; i < 512; i += 256) {
            int r = i >> 3, q = i & 7;
            *(float4*)&As[r][q*4] = *(const float4*)&g_x3[(size_t)(r0 + r)*128 + k0 + q*4];
        }
        #pragma unroll
        for (int i = threadIdx.x; i < 1024; i += 256) {
            int r = i >> 5, q = i & 31;
            *(float4*)&Bs[r][q*4] = *(const float4*)&Wln[(k0 + r)*128 + q*4];
        }
        __syncthreads();
        #pragma unroll
        for (int kk = 0; kk < 32; kk++) {
            float4 bv = *(float4*)&Bs[kk][cg*4];
            #pragma unroll
            for (int r = 0; r < 8; r++) {
                float a = As[rg*8 + r][kk];
                acc[r][0] += a * bv.x; acc[r][1] += a * bv.y;
                acc[r][2] += a * bv.z; acc[r][3] += a * bv.w;
            }
        }
        __syncthreads();
    }

    float4 bl = *(const float4*)&bln[cg*4];
    float s[4]  = {0.f, 0.f, 0.f, 0.f};
    float mx[4] = {-INFINITY, -INFINITY, -INFINITY, -INFINITY};
    #pragma unroll
    for (int r = 0; r < 8; r++) {
        int row = r0 + rg*8 + r;
        float sa = g_satt[row] * mask[row];
        float v0 = fmaxf(acc[r][0] + bl.x, 0.f) * sa;
        float v1 = fmaxf(acc[r][1] + bl.y, 0.f) * sa;
        float v2 = fmaxf(acc[r][2] + bl.z, 0.f) * sa;
        float v3 = fmaxf(acc[r][3] + bl.w, 0.f) * sa;
        s[0] += v0; s[1] += v1; s[2] += v2; s[3] += v3;
        mx[0] = fmaxf(mx[0], v0); mx[1] = fmaxf(mx[1], v1);
        mx[2] = fmaxf(mx[2], v2); mx[3] = fmaxf(mx[3], v3);
    }
    #pragma unroll
    for (int c = 0; c < 4; c++) {
        redS[rg][cg*4 + c] = s[c];
        redM[rg][cg*4 + c] = mx[c];
    }
    __syncthreads();
    if (threadIdx.x < 32) {
        int bI = r0 >> 10;
        int t  = (r0 >> 6) & 15;
        #pragma unroll
        for (int c = 0; c < 4; c++) {
            int col = threadIdx.x*4 + c;
            float ss = 0.f, mm = -INFINITY;
            #pragma unroll
            for (int g = 0; g < 8; g++) {
                ss += redS[g][col];
                mm = fmaxf(mm, redM[g][col]);
            }
            g_psum[(bI*16 + t)*HD + col] = ss;
            g_pmax[(bI*16 + t)*HD + col] = mm;
        }
    }
}

__global__ void final_reduce(float* __restrict__ out) {
    int b = blockIdx.x, h = threadIdx.x;
    float s = 0.f, mx = -INFINITY;
    #pragma unroll
    for (int t = 0; t < 16; t++) {
        s += g_psum[(b*16 + t)*HD + h];
        mx = fmaxf(mx, g_pmax[(b*16 + t)*HD + h]);
    }
    out[b*HD + h] = s * mx;
}

// ============================================================================
extern "C" void kernel_launch(void* const* d_in, const int* in_sizes, int n_in,
                              void* d_out, int out_size) {
    const float* inputs = (const float*)d_in[0];
    const float* adj    = (const float*)d_in[1];
    const float* mask   = (const float*)d_in[2];
    const float* W0     = (const float*)d_in[3];
    const float* W1     = (const float*)d_in[4];
    const float* Wg     = (const float*)d_in[5];
    const float* a      = (const float*)d_in[6];
    const float* w_sa   = (const float*)d_in[7];
    const float* b_sa   = (const float*)d_in[8];
    const float* W_ln   = (const float*)d_in[9];
    const float* b_ln   = (const float*)d_in[10];
    float* out = (float*)d_out;

    cudaFuncSetAttribute(adj_gemm_tc<0>, cudaFuncAttributeMaxDynamicSharedMemorySize, ADJ_SMEM_BYTES);
    cudaFuncSetAttribute(adj_gemm_tc<1>, cudaFuncAttributeMaxDynamicSharedMemorySize, ADJ_SMEM_BYTES);
    cudaFuncSetAttribute(gat_tc, cudaFuncAttributeMaxDynamicSharedMemorySize, GAT_SMEM_BYTES);

    const int ROWS = BB * NN;               // 16384
    dim3 gFeat(ROWS / 64);                  // 256
    dim3 gAdjTC(NN / 128, BB);              // (8,16) = 128 CTAs
    dim3 gGat(NN / 128, BB);                // (8,16) = 128 CTAs
    dim3 gWarp(ROWS / 8);                   // 2048

    // x1 = relu(adj @ (inputs @ W0)) * mask
    feat_gemm<0, 0><<<gFeat, 256>>>(inputs, W0);
    adj_gemm_tc<0><<<gAdjTC, 256, ADJ_SMEM_BYTES>>>(adj, mask);
    // x2 = x1 + relu(adj @ (x1 @ W1)) * mask
    feat_gemm<1, 0><<<gFeat, 256>>>(nullptr, W1);
    adj_gemm_tc<1><<<gAdjTC, 256, ADJ_SMEM_BYTES>>>(adj, mask);
    // GAT
    feat_gemm<2, 1><<<gFeat, 256>>>(nullptr, Wg);   // Wh = x2 @ Wg (pre-rounded)
    s12_kernel<<<gWarp, 256>>>(a);
    gat_tc<<<gGat, 256, GAT_SMEM_BYTES>>>(adj, mask);
    // epilogue
    satt_kernel<<<gWarp, 256>>>(w_sa, b_sa);
    final_gemm<<<gFeat, 256>>>(W_ln, b_ln, mask);
    final_reduce<<<BB, HD>>>(out);
}

// round 9
// speedup vs baseline: 1.1118x; 1.1118x over previous
#include <cuda_runtime.h>
#include <math.h>
#include <stdint.h>

#define BB 16
#define NN 1024
#define HD 128
#define NEGV (-9000000000000000.0f)
#define ALPHAV 0.2f

// ---------------- scratch (device globals; no allocation allowed) ----------------
__device__ float g_Y [BB*NN*HD];
__device__ float g_X1[BB*NN*HD];
__device__ float g_X2[BB*NN*HD];
__device__ float g_Wh[BB*NN*HD];
__device__ float g_x3[BB*NN*HD];
__device__ float g_s1[BB*NN];
__device__ float g_s2[BB*NN];
__device__ float g_satt[BB*NN];
__device__ float g_psum[BB*16*HD];
__device__ float g_pmax[BB*16*HD];

// ---------------- PTX helpers ----------------
__device__ __forceinline__ unsigned smem_u32(const void* p) {
    return (unsigned)__cvta_generic_to_shared(p);
}
__device__ __forceinline__ void cpa16(void* s, const void* g) {
    asm volatile("cp.async.cg.shared.global [%0], [%1], 16;" :: "r"(smem_u32(s)), "l"(g));
}
__device__ __forceinline__ void cpa_commit() { asm volatile("cp.async.commit_group;"); }
template<int N>
__device__ __forceinline__ void cpa_wait() { asm volatile("cp.async.wait_group %0;" :: "n"(N)); }
__device__ __forceinline__ unsigned f2tf(float f) {
    unsigned u; asm("cvt.rna.tf32.f32 %0, %1;" : "=r"(u) : "f"(f)); return u;
}
__device__ __forceinline__ void mma_tf32(float* c, const unsigned* a, const unsigned* b) {
    asm volatile(
        "mma.sync.aligned.m16n8k8.row.col.f32.tf32.tf32.f32 "
        "{%0,%1,%2,%3}, {%4,%5,%6,%7}, {%8,%9}, {%0,%1,%2,%3};"
        : "+f"(c[0]), "+f"(c[1]), "+f"(c[2]), "+f"(c[3])
        : "r"(a[0]), "r"(a[1]), "r"(a[2]), "r"(a[3]), "r"(b[0]), "r"(b[1]));
}

// ============================================================================
// Feature GEMM (fp32 SIMT, accuracy-critical): C = X @ W, outputs pre-rounded
// to tf32 so tensor-core consumers load raw bits with no cvt. (R3 verbatim)
// ============================================================================
template<int SRC, int DST>
__global__ __launch_bounds__(256) void feat_gemm(const float* __restrict__ Xext,
                                                 const float* __restrict__ W) {
    const float* X = (SRC == 0) ? Xext : (SRC == 1) ? (const float*)g_X1 : (const float*)g_X2;
    float* C = (DST == 0) ? (float*)g_Y : (float*)g_Wh;

    __shared__ float As[64][32];
    __shared__ float Bs[32][128];
    const int r0 = blockIdx.x * 64;
    const int rg = threadIdx.x >> 5;
    const int cg = threadIdx.x & 31;
    float acc[8][4] = {};

    for (int k0 = 0; k0 < 128; k0 += 32) {
        #pragma unroll
        for (int i = threadIdx.x; i < 512; i += 256) {
            int r = i >> 3, q = i & 7;
            *(float4*)&As[r][q*4] = *(const float4*)&X[(size_t)(r0 + r)*128 + k0 + q*4];
        }
        #pragma unroll
        for (int i = threadIdx.x; i < 1024; i += 256) {
            int r = i >> 5, q = i & 31;
            *(float4*)&Bs[r][q*4] = *(const float4*)&W[(k0 + r)*128 + q*4];
        }
        __syncthreads();
        #pragma unroll
        for (int kk = 0; kk < 32; kk++) {
            float4 bv = *(float4*)&Bs[kk][cg*4];
            #pragma unroll
            for (int r = 0; r < 8; r++) {
                float a = As[rg*8 + r][kk];
                acc[r][0] += a * bv.x; acc[r][1] += a * bv.y;
                acc[r][2] += a * bv.z; acc[r][3] += a * bv.w;
            }
        }
        __syncthreads();
    }
    #pragma unroll
    for (int r = 0; r < 8; r++) {
        float4 v;
        v.x = __uint_as_float(f2tf(acc[r][0]));
        v.y = __uint_as_float(f2tf(acc[r][1]));
        v.z = __uint_as_float(f2tf(acc[r][2]));
        v.w = __uint_as_float(f2tf(acc[r][3]));
        *(float4*)&C[(size_t)(r0 + rg*8 + r)*128 + cg*4] = v;
    }
}

// ============================================================================
// Adjacency GEMM (R4 measured-best, mma.sync tf32): CTA 128x128, 8 warps
// 4m x 2n, warp tile 32x64, 3-stage cp.async, one barrier per k-tile.
// MODE 0: g_X1 = relu(acc)*mask ; MODE 1: g_X2 = g_X1 + relu(acc)*mask
// ============================================================================
#define ADJ_A_BYTES (128*36*4)
#define ADJ_B_BYTES (32*136*4)
#define ADJ_SMEM_BYTES (3*(ADJ_A_BYTES + ADJ_B_BYTES))   // 107520

template<int MODE>
__global__ __launch_bounds__(256, 1) void adj_gemm_tc(const float* __restrict__ adj,
                                                      const float* __restrict__ mask) {
    extern __shared__ char dynsm[];
    float (*As)[128][36] = reinterpret_cast<float(*)[128][36]>(dynsm);
    float (*Bs)[32][136] = reinterpret_cast<float(*)[32][136]>(dynsm + 3*ADJ_A_BYTES);

    const int b  = blockIdx.y;
    const int r0 = blockIdx.x * 128;
    const float* A  = adj + (size_t)b*NN*NN;
    const float* Yb = (const float*)g_Y + (size_t)b*NN*HD;
    const int tid = threadIdx.x;

    auto load_stage = [&](int st, int k0) {
        #pragma unroll
        for (int i = tid; i < 1024; i += 256) {
            int r = i >> 3, q = i & 7;
            cpa16(&As[st][r][q*4], &A[(size_t)(r0 + r)*NN + k0 + q*4]);
        }
        #pragma unroll
        for (int i = tid; i < 1024; i += 256) {
            int r = i >> 5, q = i & 31;
            cpa16(&Bs[st][r][q*4], &Yb[(size_t)(k0 + r)*HD + q*4]);
        }
        cpa_commit();
    };

    load_stage(0, 0);
    load_stage(1, 32);

    const int warp = tid >> 5, lane = tid & 31;
    const int wr = (warp >> 1) * 32;
    const int wc = (warp & 1) * 64;
    const int lr = lane >> 2;
    const int lc = lane & 3;

    float acc[2][8][4];
    #pragma unroll
    for (int mt = 0; mt < 2; mt++)
        #pragma unroll
        for (int n = 0; n < 8; n++)
            #pragma unroll
            for (int q = 0; q < 4; q++) acc[mt][n][q] = 0.f;

    for (int kt = 0; kt < 32; kt++) {
        const int cur = kt % 3;
        cpa_wait<1>();
        __syncthreads();

        #pragma unroll
        for (int ks = 0; ks < 32; ks += 8) {
            unsigned af[2][4];
            #pragma unroll
            for (int mt = 0; mt < 2; mt++) {
                int r = wr + mt*16 + lr;
                af[mt][0] = f2tf(As[cur][r    ][ks + lc    ]);
                af[mt][1] = f2tf(As[cur][r + 8][ks + lc    ]);
                af[mt][2] = f2tf(As[cur][r    ][ks + lc + 4]);
                af[mt][3] = f2tf(As[cur][r + 8][ks + lc + 4]);
            }
            unsigned bf[8][2];
            #pragma unroll
            for (int n = 0; n < 8; n++) {
                int c = wc + n*8 + lr;
                bf[n][0] = __float_as_uint(Bs[cur][ks + lc    ][c]);   // pre-rounded
                bf[n][1] = __float_as_uint(Bs[cur][ks + lc + 4][c]);
            }
            #pragma unroll
            for (int mt = 0; mt < 2; mt++)
                #pragma unroll
                for (int n = 0; n < 8; n++)
                    mma_tf32(acc[mt][n], af[mt], bf[n]);
        }

        if (kt + 2 < 32) load_stage((kt + 2) % 3, (kt + 2) * 32);
    }

    #pragma unroll
    for (int mt = 0; mt < 2; mt++) {
        #pragma unroll
        for (int half = 0; half < 2; half++) {
            int row = r0 + wr + mt*16 + lr + half*8;
            float mk = mask[b*NN + row];
            size_t base = (size_t)b*NN*HD + (size_t)row*HD;
            #pragma unroll
            for (int n = 0; n < 8; n++) {
                int col = wc + n*8 + 2*lc;
                float v0 = fmaxf(acc[mt][n][half*2 + 0], 0.f) * mk;
                float v1 = fmaxf(acc[mt][n][half*2 + 1], 0.f) * mk;
                if (MODE == 1) {
                    float2 x = *(const float2*)&g_X1[base + col];
                    v0 += x.x; v1 += x.y;
                    *(float2*)&g_X2[base + col] = make_float2(v0, v1);
                } else {
                    *(float2*)&g_X1[base + col] = make_float2(v0, v1);
                }
            }
        }
    }
}

// ============================================================================
// s1/s2 per-row dots
// ============================================================================
__global__ __launch_bounds__(256) void s12_kernel(const float* __restrict__ a) {
    int row  = blockIdx.x * 8 + (threadIdx.x >> 5);
    int lane = threadIdx.x & 31;
    float4 x  = *(const float4*)&g_Wh[(size_t)row*128 + lane*4];
    float4 a1 = *(const float4*)&a[lane*4];
    float4 a2 = *(const float4*)&a[128 + lane*4];
    float d1 = x.x*a1.x + x.y*a1.y + x.z*a1.z + x.w*a1.w;
    float d2 = x.x*a2.x + x.y*a2.y + x.z*a2.z + x.w*a2.w;
    #pragma unroll
    for (int off = 16; off > 0; off >>= 1) {
        d1 += __shfl_xor_sync(0xffffffffu, d1, off);
        d2 += __shfl_xor_sync(0xffffffffu, d2, off);
    }
    if (lane == 0) { g_s1[row] = d1; g_s2[row] = d2; }
}

// ============================================================================
// GAT (R3-verbatim arithmetic — the 6.07e-4 config): 64 query rows/CTA,
// j-tiles of 32, online softmax 4 threads/row x 8 cols, P@Wh warp tile 16x64.
// ONLY change vs R3: smem moved to dynamic + 2 CTAs/SM for occupancy.
// ============================================================================
#define GATV1_WHS_BYTES (2*32*136*4)     // 34816
#define GATV1_PS_BYTES  (64*36*4)        //  9216
#define GATV1_SMEM_BYTES (GATV1_WHS_BYTES + GATV1_PS_BYTES + 4*64*4)   // 45056

__global__ __launch_bounds__(256, 2) void gat_tc(const float* __restrict__ adj,
                                                 const float* __restrict__ mask) {
    extern __shared__ char dynsm[];
    float (*Whs)[32][136] = reinterpret_cast<float(*)[32][136]>(dynsm);
    float (*Ps)[36]       = reinterpret_cast<float(*)[36]>(dynsm + GATV1_WHS_BYTES);
    float* scaleS = reinterpret_cast<float*>(dynsm + GATV1_WHS_BYTES + GATV1_PS_BYTES);
    float* lS     = scaleS + 64;
    float* s1S    = scaleS + 128;
    float* nmiS   = scaleS + 192;

    const int b  = blockIdx.y;
    const int i0 = blockIdx.x * 64;
    const float* Ab  = adj + (size_t)b*NN*NN;
    const float* Whb = (const float*)g_Wh + (size_t)b*NN*HD;

    const int tid  = threadIdx.x;
    const int warp = tid >> 5, lane = tid & 31;
    const int m0   = (warp >> 1) * 16;
    const int wc   = (warp & 1) * 64;
    const int lr   = lane >> 2, lc = lane & 3;
    const int prow = tid >> 2, psub = tid & 3;

    if (tid < 64) {
        s1S[tid]  = g_s1[b*NN + i0 + tid];
        nmiS[tid] = mask[b*NN + i0 + tid];
    }

    auto load_wh = [&](int st, int j0) {
        #pragma unroll
        for (int i = tid; i < 1024; i += 256) {
            int r = i >> 5, q = i & 31;
            cpa16(&Whs[st][r][q*4], &Whb[(size_t)(j0 + r)*HD + q*4]);
        }
        cpa_commit();
    };

    load_wh(0, 0);

    const float* arow_base = Ab + (size_t)(i0 + prow)*NN + psub*8;
    float4 pa0 = *(const float4*)&arow_base[0];
    float4 pa1 = *(const float4*)&arow_base[4];

    float acc[8][4];
    #pragma unroll
    for (int n = 0; n < 8; n++)
        #pragma unroll
        for (int q = 0; q < 4; q++) acc[n][q] = 0.f;

    float m = -INFINITY, l = 0.f;
    __syncthreads();

    for (int jt = 0; jt < 32; jt++) {
        const int cur = jt & 1;
        const int j0  = jt * 32;
        if (jt + 1 < 32) load_wh(cur ^ 1, j0 + 32);

        float s1v = s1S[prow], nmi = nmiS[prow];
        float4 s2a = *(const float4*)&g_s2[b*NN + j0 + psub*8];
        float4 s2b = *(const float4*)&g_s2[b*NN + j0 + psub*8 + 4];
        float4 nma = *(const float4*)&mask[b*NN + j0 + psub*8];
        float4 nmb = *(const float4*)&mask[b*NN + j0 + psub*8 + 4];
        float s2v[8] = {s2a.x, s2a.y, s2a.z, s2a.w, s2b.x, s2b.y, s2b.z, s2b.w};
        float nmv[8] = {nma.x, nma.y, nma.z, nma.w, nmb.x, nmb.y, nmb.z, nmb.w};
        float av[8]  = {pa0.x, pa0.y, pa0.z, pa0.w, pa1.x, pa1.y, pa1.z, pa1.w};

        float vals[8];
        float tmax = -INFINITY;
        #pragma unroll
        for (int jj = 0; jj < 8; jj++) {
            float e = s1v + s2v[jj];
            e = (e > 0.f) ? e : ALPHAV * e;
            float edge = (av[jj] > 0.f) ? (nmv[jj] * nmi) : 0.f;
            float v = (edge > 0.f) ? e : NEGV;
            vals[jj] = v;
            tmax = fmaxf(tmax, v);
        }
        tmax = fmaxf(tmax, __shfl_xor_sync(0xffffffffu, tmax, 1));
        tmax = fmaxf(tmax, __shfl_xor_sync(0xffffffffu, tmax, 2));
        float mn    = fmaxf(m, tmax);
        float scale = __expf(m - mn);
        float psum = 0.f;
        #pragma unroll
        for (int jj = 0; jj < 8; jj++) {
            float p = __expf(vals[jj] - mn);
            float pr = __uint_as_float(f2tf(p));   // rounded once; in BOTH l and P@Wh
            Ps[prow][psub*8 + jj] = pr;
            psum += pr;
        }
        psum += __shfl_xor_sync(0xffffffffu, psum, 1);
        psum += __shfl_xor_sync(0xffffffffu, psum, 2);
        l = l * scale + psum;
        m = mn;
        if (psub == 0) scaleS[prow] = scale;

        if (jt + 1 < 32) {
            pa0 = *(const float4*)&arow_base[j0 + 32];
            pa1 = *(const float4*)&arow_base[j0 + 36];
        }

        if (jt + 1 < 32) cpa_wait<1>(); else cpa_wait<0>();
        __syncthreads();

        float sc0 = scaleS[m0 + lr], sc1 = scaleS[m0 + lr + 8];
        #pragma unroll
        for (int n = 0; n < 8; n++) {
            acc[n][0] *= sc0; acc[n][1] *= sc0;
            acc[n][2] *= sc1; acc[n][3] *= sc1;
        }
        #pragma unroll
        for (int ks = 0; ks < 32; ks += 8) {
            unsigned af[4];
            af[0] = __float_as_uint(Ps[m0 + lr    ][ks + lc    ]);
            af[1] = __float_as_uint(Ps[m0 + lr + 8][ks + lc    ]);
            af[2] = __float_as_uint(Ps[m0 + lr    ][ks + lc + 4]);
            af[3] = __float_as_uint(Ps[m0 + lr + 8][ks + lc + 4]);
            unsigned bf[8][2];
            #pragma unroll
            for (int n = 0; n < 8; n++) {
                int c = wc + n*8 + lr;
                bf[n][0] = __float_as_uint(Whs[cur][ks + lc    ][c]);
                bf[n][1] = __float_as_uint(Whs[cur][ks + lc + 4][c]);
            }
            #pragma unroll
            for (int n = 0; n < 8; n++)
                mma_tf32(acc[n], af, bf[n]);
        }
        __syncthreads();
    }

    if (psub == 0) lS[prow] = l;
    __syncthreads();

    float* x3b = (float*)g_x3 + (size_t)b*NN*HD;
    #pragma unroll
    for (int half = 0; half < 2; half++) {
        int rloc = m0 + lr + half*8;
        float inv = 1.f / lS[rloc];
        float nmi = nmiS[rloc];
        size_t base = (size_t)(i0 + rloc)*HD;
        #pragma unroll
        for (int n = 0; n < 8; n++) {
            int col = wc + n*8 + 2*lc;
            float v0 = fmaxf(acc[n][half*2 + 0]*inv, 0.f) * nmi;
            float v1 = fmaxf(acc[n][half*2 + 1]*inv, 0.f) * nmi;
            *(float2*)&x3b[base + col] = make_float2(v0, v1);
        }
    }
}

// ============================================================================
// soft attention sigmoid
// ============================================================================
__global__ __launch_bounds__(256) void satt_kernel(const float* __restrict__ w_sa,
                                                   const float* __restrict__ b_sa) {
    int row  = blockIdx.x * 8 + (threadIdx.x >> 5);
    int lane = threadIdx.x & 31;
    float4 x = *(const float4*)&g_x3[(size_t)row*128 + lane*4];
    float4 w = *(const float4*)&w_sa[lane*4];
    float d = x.x*w.x + x.y*w.y + x.z*w.z + x.w*w.w;
    #pragma unroll
    for (int off = 16; off > 0; off >>= 1)
        d += __shfl_xor_sync(0xffffffffu, d, off);
    if (lane == 0) {
        float z = d + b_sa[0];
        g_satt[row] = 1.f / (1.f + __expf(-z));
    }
}

// ============================================================================
// Final layer (fp32 SIMT) + per-tile partial sum/max
// ============================================================================
__global__ __launch_bounds__(256) void final_gemm(const float* __restrict__ Wln,
                                                  const float* __restrict__ bln,
                                                  const float* __restrict__ mask) {
    __shared__ float As[64][32];
    __shared__ float Bs[32][128];
    __shared__ float redS[8][128];
    __shared__ float redM[8][128];
    const int r0 = blockIdx.x * 64;
    const int rg = threadIdx.x >> 5;
    const int cg = threadIdx.x & 31;
    float acc[8][4] = {};

    for (int k0 = 0; k0 < 128; k0 += 32) {
        #pragma unroll
        for (int i = threadIdx.x; i < 512; i += 256) {
            int r = i >> 3, q = i & 7;
            *(float4*)&As[r][q*4] = *(const float4*)&g_x3[(size_t)(r0 + r)*128 + k0 + q*4];
        }
        #pragma unroll
        for (int i = threadIdx.x; i < 1024; i += 256) {
            int r = i >> 5, q = i & 31;
            *(float4*)&Bs[r][q*4] = *(const float4*)&Wln[(k0 + r)*128 + q*4];
        }
        __syncthreads();
        #pragma unroll
        for (int kk = 0; kk < 32; kk++) {
            float4 bv = *(float4*)&Bs[kk][cg*4];
            #pragma unroll
            for (int r = 0; r < 8; r++) {
                float a = As[rg*8 + r][kk];
                acc[r][0] += a * bv.x; acc[r][1] += a * bv.y;
                acc[r][2] += a * bv.z; acc[r][3] += a * bv.w;
            }
        }
        __syncthreads();
    }

    float4 bl = *(const float4*)&bln[cg*4];
    float s[4]  = {0.f, 0.f, 0.f, 0.f};
    float mx[4] = {-INFINITY, -INFINITY, -INFINITY, -INFINITY};
    #pragma unroll
    for (int r = 0; r < 8; r++) {
        int row = r0 + rg*8 + r;
        float sa = g_satt[row] * mask[row];
        float v0 = fmaxf(acc[r][0] + bl.x, 0.f) * sa;
        float v1 = fmaxf(acc[r][1] + bl.y, 0.f) * sa;
        float v2 = fmaxf(acc[r][2] + bl.z, 0.f) * sa;
        float v3 = fmaxf(acc[r][3] + bl.w, 0.f) * sa;
        s[0] += v0; s[1] += v1; s[2] += v2; s[3] += v3;
        mx[0] = fmaxf(mx[0], v0); mx[1] = fmaxf(mx[1], v1);
        mx[2] = fmaxf(mx[2], v2); mx[3] = fmaxf(mx[3], v3);
    }
    #pragma unroll
    for (int c = 0; c < 4; c++) {
        redS[rg][cg*4 + c] = s[c];
        redM[rg][cg*4 + c] = mx[c];
    }
    __syncthreads();
    if (threadIdx.x < 32) {
        int bI = r0 >> 10;
        int t  = (r0 >> 6) & 15;
        #pragma unroll
        for (int c = 0; c < 4; c++) {
            int col = threadIdx.x*4 + c;
            float ss = 0.f, mm = -INFINITY;
            #pragma unroll
            for (int g = 0; g < 8; g++) {
                ss += redS[g][col];
                mm = fmaxf(mm, redM[g][col]);
            }
            g_psum[(bI*16 + t)*HD + col] = ss;
            g_pmax[(bI*16 + t)*HD + col] = mm;
        }
    }
}

__global__ void final_reduce(float* __restrict__ out) {
    int b = blockIdx.x, h = threadIdx.x;
    float s = 0.f, mx = -INFINITY;
    #pragma unroll
    for (int t = 0; t < 16; t++) {
        s += g_psum[(b*16 + t)*HD + h];
        mx = fmaxf(mx, g_pmax[(b*16 + t)*HD + h]);
    }
    out[b*HD + h] = s * mx;
}

// ============================================================================
extern "C" void kernel_launch(void* const* d_in, const int* in_sizes, int n_in,
                              void* d_out, int out_size) {
    const float* inputs = (const float*)d_in[0];
    const float* adj    = (const float*)d_in[1];
    const float* mask   = (const float*)d_in[2];
    const float* W0     = (const float*)d_in[3];
    const float* W1     = (const float*)d_in[4];
    const float* Wg     = (const float*)d_in[5];
    const float* a      = (const float*)d_in[6];
    const float* w_sa   = (const float*)d_in[7];
    const float* b_sa   = (const float*)d_in[8];
    const float* W_ln   = (const float*)d_in[9];
    const float* b_ln   = (const float*)d_in[10];
    float* out = (float*)d_out;

    cudaFuncSetAttribute(adj_gemm_tc<0>, cudaFuncAttributeMaxDynamicSharedMemorySize, ADJ_SMEM_BYTES);
    cudaFuncSetAttribute(adj_gemm_tc<1>, cudaFuncAttributeMaxDynamicSharedMemorySize, ADJ_SMEM_BYTES);
    cudaFuncSetAttribute(gat_tc, cudaFuncAttributeMaxDynamicSharedMemorySize, GATV1_SMEM_BYTES);

    const int ROWS = BB * NN;               // 16384
    dim3 gFeat(ROWS / 64);                  // 256
    dim3 gAdj(NN / 128, BB);                // (8,16)
    dim3 gGat(NN / 64, BB);                 // (16,16)
    dim3 gWarp(ROWS / 8);                   // 2048

    // x1 = relu(adj @ (inputs @ W0)) * mask
    feat_gemm<0, 0><<<gFeat, 256>>>(inputs, W0);
    adj_gemm_tc<0><<<gAdj, 256, ADJ_SMEM_BYTES>>>(adj, mask);
    // x2 = x1 + relu(adj @ (x1 @ W1)) * mask
    feat_gemm<1, 0><<<gFeat, 256>>>(nullptr, W1);
    adj_gemm_tc<1><<<gAdj, 256, ADJ_SMEM_BYTES>>>(adj, mask);
    // GAT
    feat_gemm<2, 1><<<gFeat, 256>>>(nullptr, Wg);   // Wh = x2 @ Wg
    s12_kernel<<<gWarp, 256>>>(a);
    gat_tc<<<gGat, 256, GATV1_SMEM_BYTES>>>(adj, mask);
    // epilogue
    satt_kernel<<<gWarp, 256>>>(w_sa, b_sa);
    final_gemm<<<gFeat, 256>>>(W_ln, b_ln, mask);
    final_reduce<<<BB, HD>>>(out);
}

// round 11
// speedup vs baseline: 1.1612x; 1.0445x over previous
#include <cuda_runtime.h>
#include <cuda_fp16.h>
#include <math.h>
#include <stdint.h>

#define BB 16
#define NN 1024
#define HD 128
#define NEGV (-9000000000000000.0f)
#define ALPHAV 0.2f

// ---------------- scratch (device globals; no allocation allowed) ----------------
__device__ __half g_adjh[(size_t)BB*NN*NN];   // fp16 adj (32 MB)
__device__ __half g_Yth[BB*HD*NN];            // fp16 (X@W)^T per batch [b][f][node]
__device__ float  g_X1[BB*NN*HD];
__device__ float  g_X2[BB*NN*HD];
__device__ float  g_Wh[BB*NN*HD];             // tf32-rounded (gat mma + s12, as R9)
__device__ float  g_x3[BB*NN*HD];
__device__ float  g_s1[BB*NN];
__device__ float  g_s2[BB*NN];
__device__ float  g_satt[BB*NN];
__device__ float  g_psum[BB*16*HD];
__device__ float  g_pmax[BB*16*HD];

// ---------------- PTX helpers ----------------
__device__ __forceinline__ unsigned smem_u32(const void* p) {
    return (unsigned)__cvta_generic_to_shared(p);
}
__device__ __forceinline__ void cpa16(void* s, const void* g) {
    asm volatile("cp.async.cg.shared.global [%0], [%1], 16;" :: "r"(smem_u32(s)), "l"(g));
}
__device__ __forceinline__ void cpa_commit() { asm volatile("cp.async.commit_group;"); }
template<int N>
__device__ __forceinline__ void cpa_wait() { asm volatile("cp.async.wait_group %0;" :: "n"(N)); }
__device__ __forceinline__ unsigned f2tf(float f) {
    unsigned u; asm("cvt.rna.tf32.f32 %0, %1;" : "=r"(u) : "f"(f)); return u;
}
__device__ __forceinline__ void mma_tf32(float* c, const unsigned* a, const unsigned* b) {
    asm volatile(
        "mma.sync.aligned.m16n8k8.row.col.f32.tf32.tf32.f32 "
        "{%0,%1,%2,%3}, {%4,%5,%6,%7}, {%8,%9}, {%0,%1,%2,%3};"
        : "+f"(c[0]), "+f"(c[1]), "+f"(c[2]), "+f"(c[3])
        : "r"(a[0]), "r"(a[1]), "r"(a[2]), "r"(a[3]), "r"(b[0]), "r"(b[1]));
}
__device__ __forceinline__ void mma_f16(float* c, const unsigned* a, const unsigned* b) {
    asm volatile(
        "mma.sync.aligned.m16n8k16.row.col.f32.f16.f16.f32 "
        "{%0,%1,%2,%3}, {%4,%5,%6,%7}, {%8,%9}, {%0,%1,%2,%3};"
        : "+f"(c[0]), "+f"(c[1]), "+f"(c[2]), "+f"(c[3])
        : "r"(a[0]), "r"(a[1]), "r"(a[2]), "r"(a[3]), "r"(b[0]), "r"(b[1]));
}

// ============================================================================
// prep_adj: one-time fp32 -> fp16 (rna) copy of adj. 11-bit significand ==
// tf32 rounding for all normal-range values.
// ============================================================================
__global__ __launch_bounds__(256) void prep_adj(const float* __restrict__ adj) {
    size_t i = ((size_t)blockIdx.x * 256 + threadIdx.x) * 8;
    float4 v0 = *(const float4*)&adj[i];
    float4 v1 = *(const float4*)&adj[i + 4];
    __half2 h[4];
    h[0] = __floats2half2_rn(v0.x, v0.y);
    h[1] = __floats2half2_rn(v0.z, v0.w);
    h[2] = __floats2half2_rn(v1.x, v1.y);
    h[3] = __floats2half2_rn(v1.z, v1.w);
    *(uint4*)&g_adjh[i] = *(uint4*)h;
}

// ============================================================================
// Feature GEMM (fp32 SIMT, R9 math): C = X @ W.
// DST=0: write fp16 TRANSPOSED per batch into g_Yth[b][f][node] (adj B operand).
// DST=1: write tf32-rounded fp32 into g_Wh (gat + s12), exactly as R9.
// ============================================================================
template<int SRC, int DST>
__global__ __launch_bounds__(256) void feat_gemm(const float* __restrict__ Xext,
                                                 const float* __restrict__ W) {
    const float* X = (SRC == 0) ? Xext : (SRC == 1) ? (const float*)g_X1 : (const float*)g_X2;

    __shared__ float As[64][32];
    __shared__ float Bs[32][128];
    __shared__ __half Ts[64][136];   // only used when DST==0
    const int r0 = blockIdx.x * 64;
    const int rg = threadIdx.x >> 5;
    const int cg = threadIdx.x & 31;
    float acc[8][4] = {};

    for (int k0 = 0; k0 < 128; k0 += 32) {
        #pragma unroll
        for (int i = threadIdx.x; i < 512; i += 256) {
            int r = i >> 3, q = i & 7;
            *(float4*)&As[r][q*4] = *(const float4*)&X[(size_t)(r0 + r)*128 + k0 + q*4];
        }
        #pragma unroll
        for (int i = threadIdx.x; i < 1024; i += 256) {
            int r = i >> 5, q = i & 31;
            *(float4*)&Bs[r][q*4] = *(const float4*)&W[(k0 + r)*128 + q*4];
        }
        __syncthreads();
        #pragma unroll
        for (int kk = 0; kk < 32; kk++) {
            float4 bv = *(float4*)&Bs[kk][cg*4];
            #pragma unroll
            for (int r = 0; r < 8; r++) {
                float a = As[rg*8 + r][kk];
                acc[r][0] += a * bv.x; acc[r][1] += a * bv.y;
                acc[r][2] += a * bv.z; acc[r][3] += a * bv.w;
            }
        }
        __syncthreads();
    }

    if constexpr (DST == 0) {
        // fp16 transpose epilogue: Ts[node-in-tile][feature] (rna rounding)
        #pragma unroll
        for (int r = 0; r < 8; r++) {
            Ts[rg*8 + r][cg*4 + 0] = __float2half_rn(acc[r][0]);
            Ts[rg*8 + r][cg*4 + 1] = __float2half_rn(acc[r][1]);
            Ts[rg*8 + r][cg*4 + 2] = __float2half_rn(acc[r][2]);
            Ts[rg*8 + r][cg*4 + 3] = __float2half_rn(acc[r][3]);
        }
        __syncthreads();
        int b  = r0 >> 10;
        int k0 = r0 & 1023;
        int f  = threadIdx.x >> 1;           // feature 0..127
        int kh = (threadIdx.x & 1) * 32;     // node sub-block
        __half* dst = (__half*)g_Yth + ((size_t)b*HD + f)*NN + k0 + kh;
        #pragma unroll
        for (int q = 0; q < 32; q += 2) {
            __half2 hv = __halves2half2(Ts[kh + q][f], Ts[kh + q + 1][f]);
            *(__half2*)&dst[q] = hv;
        }
    } else {
        #pragma unroll
        for (int r = 0; r < 8; r++) {
            float4 v;
            v.x = __uint_as_float(f2tf(acc[r][0]));
            v.y = __uint_as_float(f2tf(acc[r][1]));
            v.z = __uint_as_float(f2tf(acc[r][2]));
            v.w = __uint_as_float(f2tf(acc[r][3]));
            *(float4*)&g_Wh[(size_t)(r0 + rg*8 + r)*128 + cg*4] = v;
        }
    }
}

// ============================================================================
// Adjacency GEMM fp16 (mma.m16n8k16, fp32 acc): CTA 128x128, BK=64, 16 k-tiles,
// 8 warps 4m x 2n (warp tile 32x64), 3-stage cp.async, one barrier per tile.
// A = g_adjh rows (row-major, k contig). B = g_Yth (n-major, k contig).
// ============================================================================
#define ADJH_TILE_BYTES (128*72*2)                       // 18432 per tile (A or B)
#define ADJH_STAGE_BYTES (2*ADJH_TILE_BYTES)             // 36864
#define ADJH_SMEM_BYTES (3*ADJH_STAGE_BYTES)             // 110592

template<int MODE>
__global__ __launch_bounds__(256, 1) void adj_gemm_f16(const float* __restrict__ mask) {
    extern __shared__ char dynsm[];
    __half (*As)[128][72] = reinterpret_cast<__half(*)[128][72]>(dynsm);
    __half (*Bs)[128][72] = reinterpret_cast<__half(*)[128][72]>(dynsm + 3*ADJH_TILE_BYTES);

    const int b  = blockIdx.y;
    const int r0 = blockIdx.x * 128;
    const __half* A  = (const __half*)g_adjh + (size_t)b*NN*NN;
    const __half* Bt = (const __half*)g_Yth  + (size_t)b*HD*NN;
    const int tid = threadIdx.x;

    auto load_stage = [&](int st, int k0) {
        #pragma unroll
        for (int i = tid; i < 1024; i += 256) {
            int r = i >> 3, q = i & 7;               // 128 rows x 8 chunks of 16B
            cpa16(&As[st][r][q*8], &A[(size_t)(r0 + r)*NN + k0 + q*8]);
        }
        #pragma unroll
        for (int i = tid; i < 1024; i += 256) {
            int f = i >> 3, q = i & 7;               // 128 features x 8 chunks
            cpa16(&Bs[st][f][q*8], &Bt[(size_t)f*NN + k0 + q*8]);
        }
        cpa_commit();
    };

    load_stage(0, 0);
    load_stage(1, 64);

    const int warp = tid >> 5, lane = tid & 31;
    const int wr = (warp >> 1) * 32;     // 0,32,64,96
    const int wc = (warp & 1) * 64;      // 0,64
    const int lr = lane >> 2;            // 0..7
    const int lc = lane & 3;             // 0..3

    float acc[2][8][4];
    #pragma unroll
    for (int mt = 0; mt < 2; mt++)
        #pragma unroll
        for (int n = 0; n < 8; n++)
            #pragma unroll
            for (int q = 0; q < 4; q++) acc[mt][n][q] = 0.f;

    for (int kt = 0; kt < 16; kt++) {
        const int cur = kt % 3;
        cpa_wait<1>();
        __syncthreads();

        #pragma unroll
        for (int s = 0; s < 4; s++) {            // 4 x k16 per BK=64
            const int kb = s * 16;
            unsigned af[2][4];
            #pragma unroll
            for (int mt = 0; mt < 2; mt++) {
                int r = wr + mt*16 + lr;
                af[mt][0] = *(const unsigned*)&As[cur][r    ][kb + 2*lc    ];
                af[mt][1] = *(const unsigned*)&As[cur][r + 8][kb + 2*lc    ];
                af[mt][2] = *(const unsigned*)&As[cur][r    ][kb + 2*lc + 8];
                af[mt][3] = *(const unsigned*)&As[cur][r + 8][kb + 2*lc + 8];
            }
            unsigned bf[8][2];
            #pragma unroll
            for (int n = 0; n < 8; n++) {
                int c = wc + n*8 + lr;
                bf[n][0] = *(const unsigned*)&Bs[cur][c][kb + 2*lc    ];
                bf[n][1] = *(const unsigned*)&Bs[cur][c][kb + 2*lc + 8];
            }
            #pragma unroll
            for (int mt = 0; mt < 2; mt++)
                #pragma unroll
                for (int n = 0; n < 8; n++)
                    mma_f16(acc[mt][n], af[mt], bf[n]);
        }

        if (kt + 2 < 16) load_stage((kt + 2) % 3, (kt + 2) * 64);
    }

    #pragma unroll
    for (int mt = 0; mt < 2; mt++) {
        #pragma unroll
        for (int half = 0; half < 2; half++) {
            int row = r0 + wr + mt*16 + lr + half*8;
            float mk = mask[b*NN + row];
            size_t base = (size_t)b*NN*HD + (size_t)row*HD;
            #pragma unroll
            for (int n = 0; n < 8; n++) {
                int col = wc + n*8 + 2*lc;
                float v0 = fmaxf(acc[mt][n][half*2 + 0], 0.f) * mk;
                float v1 = fmaxf(acc[mt][n][half*2 + 1], 0.f) * mk;
                if (MODE == 1) {
                    float2 x = *(const float2*)&g_X1[base + col];
                    v0 += x.x; v1 += x.y;
                    *(float2*)&g_X2[base + col] = make_float2(v0, v1);
                } else {
                    *(float2*)&g_X1[base + col] = make_float2(v0, v1);
                }
            }
        }
    }
}

// ============================================================================
// s1/s2 per-row dots (reads tf32-rounded g_Wh — exactly as R9)
// ============================================================================
__global__ __launch_bounds__(256) void s12_kernel(const float* __restrict__ a) {
    int row  = blockIdx.x * 8 + (threadIdx.x >> 5);
    int lane = threadIdx.x & 31;
    float4 x  = *(const float4*)&g_Wh[(size_t)row*128 + lane*4];
    float4 a1 = *(const float4*)&a[lane*4];
    float4 a2 = *(const float4*)&a[128 + lane*4];
    float d1 = x.x*a1.x + x.y*a1.y + x.z*a1.z + x.w*a1.w;
    float d2 = x.x*a2.x + x.y*a2.y + x.z*a2.z + x.w*a2.w;
    #pragma unroll
    for (int off = 16; off > 0; off >>= 1) {
        d1 += __shfl_xor_sync(0xffffffffu, d1, off);
        d2 += __shfl_xor_sync(0xffffffffu, d2, off);
    }
    if (lane == 0) { g_s1[row] = d1; g_s2[row] = d2; }
}

// ============================================================================
// GAT (R9 verbatim): 64 query rows/CTA, j-tiles of 32, online softmax
// 4 threads/row x 8 cols, P@Wh tf32 warp tile 16x64, 2 CTAs/SM.
// ============================================================================
#define GATV1_WHS_BYTES (2*32*136*4)     // 34816
#define GATV1_PS_BYTES  (64*36*4)        //  9216
#define GATV1_SMEM_BYTES (GATV1_WHS_BYTES + GATV1_PS_BYTES + 4*64*4)   // 45056

__global__ __launch_bounds__(256, 2) void gat_tc(const float* __restrict__ adj,
                                                 const float* __restrict__ mask) {
    extern __shared__ char dynsm[];
    float (*Whs)[32][136] = reinterpret_cast<float(*)[32][136]>(dynsm);
    float (*Ps)[36]       = reinterpret_cast<float(*)[36]>(dynsm + GATV1_WHS_BYTES);
    float* scaleS = reinterpret_cast<float*>(dynsm + GATV1_WHS_BYTES + GATV1_PS_BYTES);
    float* lS     = scaleS + 64;
    float* s1S    = scaleS + 128;
    float* nmiS   = scaleS + 192;

    const int b  = blockIdx.y;
    const int i0 = blockIdx.x * 64;
    const float* Ab  = adj + (size_t)b*NN*NN;
    const float* Whb = (const float*)g_Wh + (size_t)b*NN*HD;

    const int tid  = threadIdx.x;
    const int warp = tid >> 5, lane = tid & 31;
    const int m0   = (warp >> 1) * 16;
    const int wc   = (warp & 1) * 64;
    const int lr   = lane >> 2, lc = lane & 3;
    const int prow = tid >> 2, psub = tid & 3;

    if (tid < 64) {
        s1S[tid]  = g_s1[b*NN + i0 + tid];
        nmiS[tid] = mask[b*NN + i0 + tid];
    }

    auto load_wh = [&](int st, int j0) {
        #pragma unroll
        for (int i = tid; i < 1024; i += 256) {
            int r = i >> 5, q = i & 31;
            cpa16(&Whs[st][r][q*4], &Whb[(size_t)(j0 + r)*HD + q*4]);
        }
        cpa_commit();
    };

    load_wh(0, 0);

    const float* arow_base = Ab + (size_t)(i0 + prow)*NN + psub*8;
    float4 pa0 = *(const float4*)&arow_base[0];
    float4 pa1 = *(const float4*)&arow_base[4];

    float acc[8][4];
    #pragma unroll
    for (int n = 0; n < 8; n++)
        #pragma unroll
        for (int q = 0; q < 4; q++) acc[n][q] = 0.f;

    float m = -INFINITY, l = 0.f;
    __syncthreads();

    for (int jt = 0; jt < 32; jt++) {
        const int cur = jt & 1;
        const int j0  = jt * 32;
        if (jt + 1 < 32) load_wh(cur ^ 1, j0 + 32);

        float s1v = s1S[prow], nmi = nmiS[prow];
        float4 s2a = *(const float4*)&g_s2[b*NN + j0 + psub*8];
        float4 s2b = *(const float4*)&g_s2[b*NN + j0 + psub*8 + 4];
        float4 nma = *(const float4*)&mask[b*NN + j0 + psub*8];
        float4 nmb = *(const float4*)&mask[b*NN + j0 + psub*8 + 4];
        float s2v[8] = {s2a.x, s2a.y, s2a.z, s2a.w, s2b.x, s2b.y, s2b.z, s2b.w};
        float nmv[8] = {nma.x, nma.y, nma.z, nma.w, nmb.x, nmb.y, nmb.z, nmb.w};
        float av[8]  = {pa0.x, pa0.y, pa0.z, pa0.w, pa1.x, pa1.y, pa1.z, pa1.w};

        float vals[8];
        float tmax = -INFINITY;
        #pragma unroll
        for (int jj = 0; jj < 8; jj++) {
            float e = s1v + s2v[jj];
            e = (e > 0.f) ? e : ALPHAV * e;
            float edge = (av[jj] > 0.f) ? (nmv[jj] * nmi) : 0.f;
            float v = (edge > 0.f) ? e : NEGV;
            vals[jj] = v;
            tmax = fmaxf(tmax, v);
        }
        tmax = fmaxf(tmax, __shfl_xor_sync(0xffffffffu, tmax, 1));
        tmax = fmaxf(tmax, __shfl_xor_sync(0xffffffffu, tmax, 2));
        float mn    = fmaxf(m, tmax);
        float scale = __expf(m - mn);
        float psum = 0.f;
        #pragma unroll
        for (int jj = 0; jj < 8; jj++) {
            float p = __expf(vals[jj] - mn);
            float pr = __uint_as_float(f2tf(p));   // rounded once; in BOTH l and P@Wh
            Ps[prow][psub*8 + jj] = pr;
            psum += pr;
        }
        psum += __shfl_xor_sync(0xffffffffu, psum, 1);
        psum += __shfl_xor_sync(0xffffffffu, psum, 2);
        l = l * scale + psum;
        m = mn;
        if (psub == 0) scaleS[prow] = scale;

        if (jt + 1 < 32) {
            pa0 = *(const float4*)&arow_base[j0 + 32];
            pa1 = *(const float4*)&arow_base[j0 + 36];
        }

        if (jt + 1 < 32) cpa_wait<1>(); else cpa_wait<0>();
        __syncthreads();

        float sc0 = scaleS[m0 + lr], sc1 = scaleS[m0 + lr + 8];
        #pragma unroll
        for (int n = 0; n < 8; n++) {
            acc[n][0] *= sc0; acc[n][1] *= sc0;
            acc[n][2] *= sc1; acc[n][3] *= sc1;
        }
        #pragma unroll
        for (int ks = 0; ks < 32; ks += 8) {
            unsigned af[4];
            af[0] = __float_as_uint(Ps[m0 + lr    ][ks + lc    ]);
            af[1] = __float_as_uint(Ps[m0 + lr + 8][ks + lc    ]);
            af[2] = __float_as_uint(Ps[m0 + lr    ][ks + lc + 4]);
            af[3] = __float_as_uint(Ps[m0 + lr + 8][ks + lc + 4]);
            unsigned bf[8][2];
            #pragma unroll
            for (int n = 0; n < 8; n++) {
                int c = wc + n*8 + lr;
                bf[n][0] = __float_as_uint(Whs[cur][ks + lc    ][c]);
                bf[n][1] = __float_as_uint(Whs[cur][ks + lc + 4][c]);
            }
            #pragma unroll
            for (int n = 0; n < 8; n++)
                mma_tf32(acc[n], af, bf[n]);
        }
        __syncthreads();
    }

    if (psub == 0) lS[prow] = l;
    __syncthreads();

    float* x3b = (float*)g_x3 + (size_t)b*NN*HD;
    #pragma unroll
    for (int half = 0; half < 2; half++) {
        int rloc = m0 + lr + half*8;
        float inv = 1.f / lS[rloc];
        float nmi = nmiS[rloc];
        size_t base = (size_t)(i0 + rloc)*HD;
        #pragma unroll
        for (int n = 0; n < 8; n++) {
            int col = wc + n*8 + 2*lc;
            float v0 = fmaxf(acc[n][half*2 + 0]*inv, 0.f) * nmi;
            float v1 = fmaxf(acc[n][half*2 + 1]*inv, 0.f) * nmi;
            *(float2*)&x3b[base + col] = make_float2(v0, v1);
        }
    }
}

// ============================================================================
// soft attention sigmoid
// ============================================================================
__global__ __launch_bounds__(256) void satt_kernel(const float* __restrict__ w_sa,
                                                   const float* __restrict__ b_sa) {
    int row  = blockIdx.x * 8 + (threadIdx.x >> 5);
    int lane = threadIdx.x & 31;
    float4 x = *(const float4*)&g_x3[(size_t)row*128 + lane*4];
    float4 w = *(const float4*)&w_sa[lane*4];
    float d = x.x*w.x + x.y*w.y + x.z*w.z + x.w*w.w;
    #pragma unroll
    for (int off = 16; off > 0; off >>= 1)
        d += __shfl_xor_sync(0xffffffffu, d, off);
    if (lane == 0) {
        float z = d + b_sa[0];
        g_satt[row] = 1.f / (1.f + __expf(-z));
    }
}

// ============================================================================
// Final layer (fp32 SIMT) + per-tile partial sum/max
// ============================================================================
__global__ __launch_bounds__(256) void final_gemm(const float* __restrict__ Wln,
                                                  const float* __restrict__ bln,
                                                  const float* __restrict__ mask) {
    __shared__ float As[64][32];
    __shared__ float Bs[32][128];
    __shared__ float redS[8][128];
    __shared__ float redM[8][128];
    const int r0 = blockIdx.x * 64;
    const int rg = threadIdx.x >> 5;
    const int cg = threadIdx.x & 31;
    float acc[8][4] = {};

    for (int k0 = 0; k0 < 128; k0 += 32) {
        #pragma unroll
        for (int i = threadIdx.x; i < 512; i += 256) {
            int r = i >> 3, q = i & 7;
            *(float4*)&As[r][q*4] = *(const float4*)&g_x3[(size_t)(r0 + r)*128 + k0 + q*4];
        }
        #pragma unroll
        for (int i = threadIdx.x; i < 1024; i += 256) {
            int r = i >> 5, q = i & 31;
            *(float4*)&Bs[r][q*4] = *(const float4*)&Wln[(k0 + r)*128 + q*4];
        }
        __syncthreads();
        #pragma unroll
        for (int kk = 0; kk < 32; kk++) {
            float4 bv = *(float4*)&Bs[kk][cg*4];
            #pragma unroll
            for (int r = 0; r < 8; r++) {
                float a = As[rg*8 + r][kk];
                acc[r][0] += a * bv.x; acc[r][1] += a * bv.y;
                acc[r][2] += a * bv.z; acc[r][3] += a * bv.w;
            }
        }
        __syncthreads();
    }

    float4 bl = *(const float4*)&bln[cg*4];
    float s[4]  = {0.f, 0.f, 0.f, 0.f};
    float mx[4] = {-INFINITY, -INFINITY, -INFINITY, -INFINITY};
    #pragma unroll
    for (int r = 0; r < 8; r++) {
        int row = r0 + rg*8 + r;
        float sa = g_satt[row] * mask[row];
        float v0 = fmaxf(acc[r][0] + bl.x, 0.f) * sa;
        float v1 = fmaxf(acc[r][1] + bl.y, 0.f) * sa;
        float v2 = fmaxf(acc[r][2] + bl.z, 0.f) * sa;
        float v3 = fmaxf(acc[r][3] + bl.w, 0.f) * sa;
        s[0] += v0; s[1] += v1; s[2] += v2; s[3] += v3;
        mx[0] = fmaxf(mx[0], v0); mx[1] = fmaxf(mx[1], v1);
        mx[2] = fmaxf(mx[2], v2); mx[3] = fmaxf(mx[3], v3);
    }
    #pragma unroll
    for (int c = 0; c < 4; c++) {
        redS[rg][cg*4 + c] = s[c];
        redM[rg][cg*4 + c] = mx[c];
    }
    __syncthreads();
    if (threadIdx.x < 32) {
        int bI = r0 >> 10;
        int t  = (r0 >> 6) & 15;
        #pragma unroll
        for (int c = 0; c < 4; c++) {
            int col = threadIdx.x*4 + c;
            float ss = 0.f, mm = -INFINITY;
            #pragma unroll
            for (int g = 0; g < 8; g++) {
                ss += redS[g][col];
                mm = fmaxf(mm, redM[g][col]);
            }
            g_psum[(bI*16 + t)*HD + col] = ss;
            g_pmax[(bI*16 + t)*HD + col] = mm;
        }
    }
}

__global__ void final_reduce(float* __restrict__ out) {
    int b = blockIdx.x, h = threadIdx.x;
    float s = 0.f, mx = -INFINITY;
    #pragma unroll
    for (int t = 0; t < 16; t++) {
        s += g_psum[(b*16 + t)*HD + h];
        mx = fmaxf(mx, g_pmax[(b*16 + t)*HD + h]);
    }
    out[b*HD + h] = s * mx;
}

// ============================================================================
extern "C" void kernel_launch(void* const* d_in, const int* in_sizes, int n_in,
                              void* d_out, int out_size) {
    const float* inputs = (const float*)d_in[0];
    const float* adj    = (const float*)d_in[1];
    const float* mask   = (const float*)d_in[2];
    const float* W0     = (const float*)d_in[3];
    const float* W1     = (const float*)d_in[4];
    const float* Wg     = (const float*)d_in[5];
    const float* a      = (const float*)d_in[6];
    const float* w_sa   = (const float*)d_in[7];
    const float* b_sa   = (const float*)d_in[8];
    const float* W_ln   = (const float*)d_in[9];
    const float* b_ln   = (const float*)d_in[10];
    float* out = (float*)d_out;

    cudaFuncSetAttribute(adj_gemm_f16<0>, cudaFuncAttributeMaxDynamicSharedMemorySize, ADJH_SMEM_BYTES);
    cudaFuncSetAttribute(adj_gemm_f16<1>, cudaFuncAttributeMaxDynamicSharedMemorySize, ADJH_SMEM_BYTES);
    cudaFuncSetAttribute(gat_tc, cudaFuncAttributeMaxDynamicSharedMemorySize, GATV1_SMEM_BYTES);

    const int ROWS = BB * NN;               // 16384
    dim3 gFeat(ROWS / 64);                  // 256
    dim3 gAdj(NN / 128, BB);                // (8,16)
    dim3 gGat(NN / 64, BB);                 // (16,16)
    dim3 gWarp(ROWS / 8);                   // 2048

    prep_adj<<<(BB*NN*NN)/(256*8), 256>>>(adj);   // 8192 blocks

    // x1 = relu(adj @ (inputs @ W0)) * mask
    feat_gemm<0, 0><<<gFeat, 256>>>(inputs, W0);
    adj_gemm_f16<0><<<gAdj, 256, ADJH_SMEM_BYTES>>>(mask);
    // x2 = x1 + relu(adj @ (x1 @ W1)) * mask
    feat_gemm<1, 0><<<gFeat, 256>>>(nullptr, W1);
    adj_gemm_f16<1><<<gAdj, 256, ADJH_SMEM_BYTES>>>(mask);
    // GAT
    feat_gemm<2, 1><<<gFeat, 256>>>(nullptr, Wg);   // Wh (tf32-rounded fp32)
    s12_kernel<<<gWarp, 256>>>(a);
    gat_tc<<<gGat, 256, GATV1_SMEM_BYTES>>>(adj, mask);
    // epilogue
    satt_kernel<<<gWarp, 256>>>(w_sa, b_sa);
    final_gemm<<<gFeat, 256>>>(W_ln, b_ln, mask);
    final_reduce<<<BB, HD>>>(out);
}

// round 12
// speedup vs baseline: 1.1827x; 1.0185x over previous
#include <cuda_runtime.h>
#include <cuda_fp16.h>
#include <math.h>
#include <stdint.h>

#define BB 16
#define NN 1024
#define HD 128
#define NEGV (-9000000000000000.0f)
#define ALPHAV 0.2f

// ---------------- scratch (device globals; no allocation allowed) ----------------
__device__ __half g_adjh[(size_t)BB*NN*NN];   // fp16 adj (32 MB)
__device__ __half g_Yth[BB*HD*NN];            // fp16 (X@W)^T per batch [b][f][node]
__device__ float  g_X1[BB*NN*HD];
__device__ float  g_X2[BB*NN*HD];
__device__ float  g_Wh[BB*NN*HD];             // tf32-rounded (gat mma)
__device__ float  g_x3[BB*NN*HD];
__device__ float  g_s1[BB*NN];
__device__ float  g_s2[BB*NN];
__device__ float  g_satt[BB*NN];
__device__ float  g_psum[BB*16*HD];
__device__ float  g_pmax[BB*16*HD];

// ---------------- PTX helpers ----------------
__device__ __forceinline__ unsigned smem_u32(const void* p) {
    return (unsigned)__cvta_generic_to_shared(p);
}
__device__ __forceinline__ void cpa16(void* s, const void* g) {
    asm volatile("cp.async.cg.shared.global [%0], [%1], 16;" :: "r"(smem_u32(s)), "l"(g));
}
__device__ __forceinline__ void cpa_commit() { asm volatile("cp.async.commit_group;"); }
template<int N>
__device__ __forceinline__ void cpa_wait() { asm volatile("cp.async.wait_group %0;" :: "n"(N)); }
__device__ __forceinline__ unsigned f2tf(float f) {
    unsigned u; asm("cvt.rna.tf32.f32 %0, %1;" : "=r"(u) : "f"(f)); return u;
}
__device__ __forceinline__ void mma_tf32(float* c, const unsigned* a, const unsigned* b) {
    asm volatile(
        "mma.sync.aligned.m16n8k8.row.col.f32.tf32.tf32.f32 "
        "{%0,%1,%2,%3}, {%4,%5,%6,%7}, {%8,%9}, {%0,%1,%2,%3};"
        : "+f"(c[0]), "+f"(c[1]), "+f"(c[2]), "+f"(c[3])
        : "r"(a[0]), "r"(a[1]), "r"(a[2]), "r"(a[3]), "r"(b[0]), "r"(b[1]));
}
__device__ __forceinline__ void mma_f16(float* c, const unsigned* a, const unsigned* b) {
    asm volatile(
        "mma.sync.aligned.m16n8k16.row.col.f32.f16.f16.f32 "
        "{%0,%1,%2,%3}, {%4,%5,%6,%7}, {%8,%9}, {%0,%1,%2,%3};"
        : "+f"(c[0]), "+f"(c[1]), "+f"(c[2]), "+f"(c[3])
        : "r"(a[0]), "r"(a[1]), "r"(a[2]), "r"(a[3]), "r"(b[0]), "r"(b[1]));
}

// ============================================================================
// prep_adj: one-time fp32 -> fp16 (rna) copy of adj.
// ============================================================================
__global__ __launch_bounds__(256) void prep_adj(const float* __restrict__ adj) {
    size_t i = ((size_t)blockIdx.x * 256 + threadIdx.x) * 8;
    float4 v0 = *(const float4*)&adj[i];
    float4 v1 = *(const float4*)&adj[i + 4];
    __half2 h[4];
    h[0] = __floats2half2_rn(v0.x, v0.y);
    h[1] = __floats2half2_rn(v0.z, v0.w);
    h[2] = __floats2half2_rn(v1.x, v1.y);
    h[3] = __floats2half2_rn(v1.z, v1.w);
    *(uint4*)&g_adjh[i] = *(uint4*)h;
}

// ============================================================================
// Feature GEMM v2 (fp32 SIMT, identical FMA order to R11): C = X @ W.
// cp.async double-buffered, dynamic smem, 2 CTAs/SM.
// DST=0: fp16 transposed into g_Yth (Ts overlays pipeline buffers).
// DST=1: tf32-rounded fp32 into g_Wh + FUSED s1/s2 (bit-identical to s12_kernel).
// ============================================================================
#define FEAT_AS_BYTES (2*64*36*4)     // 18432
#define FEAT_BS_BYTES (2*32*136*4)    // 34816
#define FEAT_SMEM_BYTES (FEAT_AS_BYTES + FEAT_BS_BYTES)   // 53248

template<int SRC, int DST>
__global__ __launch_bounds__(256, 2) void feat_gemm(const float* __restrict__ Xext,
                                                    const float* __restrict__ W,
                                                    const float* __restrict__ avec) {
    extern __shared__ char dynsm[];
    float (*As)[64][36]  = reinterpret_cast<float(*)[64][36]>(dynsm);
    float (*Bs)[32][136] = reinterpret_cast<float(*)[32][136]>(dynsm + FEAT_AS_BYTES);

    const float* X = (SRC == 0) ? Xext : (SRC == 1) ? (const float*)g_X1 : (const float*)g_X2;

    const int tid = threadIdx.x;
    const int r0 = blockIdx.x * 64;
    const int rg = tid >> 5;
    const int cg = tid & 31;

    auto load_stage = [&](int st, int k0) {
        #pragma unroll
        for (int i = tid; i < 512; i += 256) {
            int r = i >> 3, q = i & 7;
            cpa16(&As[st][r][q*4], &X[(size_t)(r0 + r)*128 + k0 + q*4]);
        }
        #pragma unroll
        for (int i = tid; i < 1024; i += 256) {
            int r = i >> 5, q = i & 31;
            cpa16(&Bs[st][r][q*4], &W[(k0 + r)*128 + q*4]);
        }
        cpa_commit();
    };

    load_stage(0, 0);
    load_stage(1, 32);

    float acc[8][4] = {};

    #pragma unroll
    for (int kt = 0; kt < 4; kt++) {
        const int cur = kt & 1;
        if (kt < 3) cpa_wait<1>(); else cpa_wait<0>();
        __syncthreads();
        #pragma unroll
        for (int kk = 0; kk < 32; kk++) {
            float4 bv = *(float4*)&Bs[cur][kk][cg*4];
            #pragma unroll
            for (int r = 0; r < 8; r++) {
                float a = As[cur][rg*8 + r][kk];
                acc[r][0] += a * bv.x; acc[r][1] += a * bv.y;
                acc[r][2] += a * bv.z; acc[r][3] += a * bv.w;
            }
        }
        __syncthreads();
        if (kt + 2 < 4) load_stage(cur, (kt + 2) * 32);
    }

    if constexpr (DST == 0) {
        // fp16 transpose epilogue: Ts overlays the As/Bs region (compute done)
        __half (*Ts)[136] = reinterpret_cast<__half(*)[136]>(dynsm);
        #pragma unroll
        for (int r = 0; r < 8; r++) {
            Ts[rg*8 + r][cg*4 + 0] = __float2half_rn(acc[r][0]);
            Ts[rg*8 + r][cg*4 + 1] = __float2half_rn(acc[r][1]);
            Ts[rg*8 + r][cg*4 + 2] = __float2half_rn(acc[r][2]);
            Ts[rg*8 + r][cg*4 + 3] = __float2half_rn(acc[r][3]);
        }
        __syncthreads();
        int b  = r0 >> 10;
        int k0 = r0 & 1023;
        int f  = tid >> 1;
        int kh = (tid & 1) * 32;
        __half* dst = (__half*)g_Yth + ((size_t)b*HD + f)*NN + k0 + kh;
        #pragma unroll
        for (int q = 0; q < 32; q += 2) {
            __half2 hv = __halves2half2(Ts[kh + q][f], Ts[kh + q + 1][f]);
            *(__half2*)&dst[q] = hv;
        }
    } else {
        // tf32-round, store Wh, and fuse s1/s2 (same expression + reduce order
        // as the old s12_kernel on the same rounded values -> bit-identical)
        float rr[8][4];
        #pragma unroll
        for (int r = 0; r < 8; r++) {
            rr[r][0] = __uint_as_float(f2tf(acc[r][0]));
            rr[r][1] = __uint_as_float(f2tf(acc[r][1]));
            rr[r][2] = __uint_as_float(f2tf(acc[r][2]));
            rr[r][3] = __uint_as_float(f2tf(acc[r][3]));
            *(float4*)&g_Wh[(size_t)(r0 + rg*8 + r)*128 + cg*4] =
                make_float4(rr[r][0], rr[r][1], rr[r][2], rr[r][3]);
        }
        float4 a1 = *(const float4*)&avec[cg*4];
        float4 a2 = *(const float4*)&avec[128 + cg*4];
        #pragma unroll
        for (int r = 0; r < 8; r++) {
            float d1 = rr[r][0]*a1.x + rr[r][1]*a1.y + rr[r][2]*a1.z + rr[r][3]*a1.w;
            float d2 = rr[r][0]*a2.x + rr[r][1]*a2.y + rr[r][2]*a2.z + rr[r][3]*a2.w;
            #pragma unroll
            for (int off = 16; off > 0; off >>= 1) {
                d1 += __shfl_xor_sync(0xffffffffu, d1, off);
                d2 += __shfl_xor_sync(0xffffffffu, d2, off);
            }
            if (cg == 0) {
                int row = r0 + rg*8 + r;
                g_s1[row] = d1;
                g_s2[row] = d2;
            }
        }
    }
}

// ============================================================================
// Adjacency GEMM fp16 (R11 verbatim): CTA 128x128, BK=64, 16 k-tiles,
// 8 warps 4m x 2n, 3-stage cp.async.
// ============================================================================
#define ADJH_TILE_BYTES (128*72*2)
#define ADJH_STAGE_BYTES (2*ADJH_TILE_BYTES)
#define ADJH_SMEM_BYTES (3*ADJH_STAGE_BYTES)             // 110592

template<int MODE>
__global__ __launch_bounds__(256, 1) void adj_gemm_f16(const float* __restrict__ mask) {
    extern __shared__ char dynsm[];
    __half (*As)[128][72] = reinterpret_cast<__half(*)[128][72]>(dynsm);
    __half (*Bs)[128][72] = reinterpret_cast<__half(*)[128][72]>(dynsm + 3*ADJH_TILE_BYTES);

    const int b  = blockIdx.y;
    const int r0 = blockIdx.x * 128;
    const __half* A  = (const __half*)g_adjh + (size_t)b*NN*NN;
    const __half* Bt = (const __half*)g_Yth  + (size_t)b*HD*NN;
    const int tid = threadIdx.x;

    auto load_stage = [&](int st, int k0) {
        #pragma unroll
        for (int i = tid; i < 1024; i += 256) {
            int r = i >> 3, q = i & 7;
            cpa16(&As[st][r][q*8], &A[(size_t)(r0 + r)*NN + k0 + q*8]);
        }
        #pragma unroll
        for (int i = tid; i < 1024; i += 256) {
            int f = i >> 3, q = i & 7;
            cpa16(&Bs[st][f][q*8], &Bt[(size_t)f*NN + k0 + q*8]);
        }
        cpa_commit();
    };

    load_stage(0, 0);
    load_stage(1, 64);

    const int warp = tid >> 5, lane = tid & 31;
    const int wr = (warp >> 1) * 32;
    const int wc = (warp & 1) * 64;
    const int lr = lane >> 2;
    const int lc = lane & 3;

    float acc[2][8][4];
    #pragma unroll
    for (int mt = 0; mt < 2; mt++)
        #pragma unroll
        for (int n = 0; n < 8; n++)
            #pragma unroll
            for (int q = 0; q < 4; q++) acc[mt][n][q] = 0.f;

    for (int kt = 0; kt < 16; kt++) {
        const int cur = kt % 3;
        cpa_wait<1>();
        __syncthreads();

        #pragma unroll
        for (int s = 0; s < 4; s++) {
            const int kb = s * 16;
            unsigned af[2][4];
            #pragma unroll
            for (int mt = 0; mt < 2; mt++) {
                int r = wr + mt*16 + lr;
                af[mt][0] = *(const unsigned*)&As[cur][r    ][kb + 2*lc    ];
                af[mt][1] = *(const unsigned*)&As[cur][r + 8][kb + 2*lc    ];
                af[mt][2] = *(const unsigned*)&As[cur][r    ][kb + 2*lc + 8];
                af[mt][3] = *(const unsigned*)&As[cur][r + 8][kb + 2*lc + 8];
            }
            unsigned bf[8][2];
            #pragma unroll
            for (int n = 0; n < 8; n++) {
                int c = wc + n*8 + lr;
                bf[n][0] = *(const unsigned*)&Bs[cur][c][kb + 2*lc    ];
                bf[n][1] = *(const unsigned*)&Bs[cur][c][kb + 2*lc + 8];
            }
            #pragma unroll
            for (int mt = 0; mt < 2; mt++)
                #pragma unroll
                for (int n = 0; n < 8; n++)
                    mma_f16(acc[mt][n], af[mt], bf[n]);
        }

        if (kt + 2 < 16) load_stage((kt + 2) % 3, (kt + 2) * 64);
    }

    #pragma unroll
    for (int mt = 0; mt < 2; mt++) {
        #pragma unroll
        for (int half = 0; half < 2; half++) {
            int row = r0 + wr + mt*16 + lr + half*8;
            float mk = mask[b*NN + row];
            size_t base = (size_t)b*NN*HD + (size_t)row*HD;
            #pragma unroll
            for (int n = 0; n < 8; n++) {
                int col = wc + n*8 + 2*lc;
                float v0 = fmaxf(acc[mt][n][half*2 + 0], 0.f) * mk;
                float v1 = fmaxf(acc[mt][n][half*2 + 1], 0.f) * mk;
                if (MODE == 1) {
                    float2 x = *(const float2*)&g_X1[base + col];
                    v0 += x.x; v1 += x.y;
                    *(float2*)&g_X2[base + col] = make_float2(v0, v1);
                } else {
                    *(float2*)&g_X1[base + col] = make_float2(v0, v1);
                }
            }
        }
    }
}

// ============================================================================
// GAT (R9/R11 verbatim): 64 query rows/CTA, j-tiles of 32, online softmax
// 4 threads/row x 8 cols, P@Wh tf32 warp tile 16x64, 2 CTAs/SM.
// ============================================================================
#define GATV1_WHS_BYTES (2*32*136*4)
#define GATV1_PS_BYTES  (64*36*4)
#define GATV1_SMEM_BYTES (GATV1_WHS_BYTES + GATV1_PS_BYTES + 4*64*4)   // 45056

__global__ __launch_bounds__(256, 2) void gat_tc(const float* __restrict__ adj,
                                                 const float* __restrict__ mask) {
    extern __shared__ char dynsm[];
    float (*Whs)[32][136] = reinterpret_cast<float(*)[32][136]>(dynsm);
    float (*Ps)[36]       = reinterpret_cast<float(*)[36]>(dynsm + GATV1_WHS_BYTES);
    float* scaleS = reinterpret_cast<float*>(dynsm + GATV1_WHS_BYTES + GATV1_PS_BYTES);
    float* lS     = scaleS + 64;
    float* s1S    = scaleS + 128;
    float* nmiS   = scaleS + 192;

    const int b  = blockIdx.y;
    const int i0 = blockIdx.x * 64;
    const float* Ab  = adj + (size_t)b*NN*NN;
    const float* Whb = (const float*)g_Wh + (size_t)b*NN*HD;

    const int tid  = threadIdx.x;
    const int warp = tid >> 5, lane = tid & 31;
    const int m0   = (warp >> 1) * 16;
    const int wc   = (warp & 1) * 64;
    const int lr   = lane >> 2, lc = lane & 3;
    const int prow = tid >> 2, psub = tid & 3;

    if (tid < 64) {
        s1S[tid]  = g_s1[b*NN + i0 + tid];
        nmiS[tid] = mask[b*NN + i0 + tid];
    }

    auto load_wh = [&](int st, int j0) {
        #pragma unroll
        for (int i = tid; i < 1024; i += 256) {
            int r = i >> 5, q = i & 31;
            cpa16(&Whs[st][r][q*4], &Whb[(size_t)(j0 + r)*HD + q*4]);
        }
        cpa_commit();
    };

    load_wh(0, 0);

    const float* arow_base = Ab + (size_t)(i0 + prow)*NN + psub*8;
    float4 pa0 = *(const float4*)&arow_base[0];
    float4 pa1 = *(const float4*)&arow_base[4];

    float acc[8][4];
    #pragma unroll
    for (int n = 0; n < 8; n++)
        #pragma unroll
        for (int q = 0; q < 4; q++) acc[n][q] = 0.f;

    float m = -INFINITY, l = 0.f;
    __syncthreads();

    for (int jt = 0; jt < 32; jt++) {
        const int cur = jt & 1;
        const int j0  = jt * 32;
        if (jt + 1 < 32) load_wh(cur ^ 1, j0 + 32);

        float s1v = s1S[prow], nmi = nmiS[prow];
        float4 s2a = *(const float4*)&g_s2[b*NN + j0 + psub*8];
        float4 s2b = *(const float4*)&g_s2[b*NN + j0 + psub*8 + 4];
        float4 nma = *(const float4*)&mask[b*NN + j0 + psub*8];
        float4 nmb = *(const float4*)&mask[b*NN + j0 + psub*8 + 4];
        float s2v[8] = {s2a.x, s2a.y, s2a.z, s2a.w, s2b.x, s2b.y, s2b.z, s2b.w};
        float nmv[8] = {nma.x, nma.y, nma.z, nma.w, nmb.x, nmb.y, nmb.z, nmb.w};
        float av[8]  = {pa0.x, pa0.y, pa0.z, pa0.w, pa1.x, pa1.y, pa1.z, pa1.w};

        float vals[8];
        float tmax = -INFINITY;
        #pragma unroll
        for (int jj = 0; jj < 8; jj++) {
            float e = s1v + s2v[jj];
            e = (e > 0.f) ? e : ALPHAV * e;
            float edge = (av[jj] > 0.f) ? (nmv[jj] * nmi) : 0.f;
            float v = (edge > 0.f) ? e : NEGV;
            vals[jj] = v;
            tmax = fmaxf(tmax, v);
        }
        tmax = fmaxf(tmax, __shfl_xor_sync(0xffffffffu, tmax, 1));
        tmax = fmaxf(tmax, __shfl_xor_sync(0xffffffffu, tmax, 2));
        float mn    = fmaxf(m, tmax);
        float scale = __expf(m - mn);
        float psum = 0.f;
        #pragma unroll
        for (int jj = 0; jj < 8; jj++) {
            float p = __expf(vals[jj] - mn);
            float pr = __uint_as_float(f2tf(p));   // rounded once; in BOTH l and P@Wh
            Ps[prow][psub*8 + jj] = pr;
            psum += pr;
        }
        psum += __shfl_xor_sync(0xffffffffu, psum, 1);
        psum += __shfl_xor_sync(0xffffffffu, psum, 2);
        l = l * scale + psum;
        m = mn;
        if (psub == 0) scaleS[prow] = scale;

        if (jt + 1 < 32) {
            pa0 = *(const float4*)&arow_base[j0 + 32];
            pa1 = *(const float4*)&arow_base[j0 + 36];
        }

        if (jt + 1 < 32) cpa_wait<1>(); else cpa_wait<0>();
        __syncthreads();

        float sc0 = scaleS[m0 + lr], sc1 = scaleS[m0 + lr + 8];
        #pragma unroll
        for (int n = 0; n < 8; n++) {
            acc[n][0] *= sc0; acc[n][1] *= sc0;
            acc[n][2] *= sc1; acc[n][3] *= sc1;
        }
        #pragma unroll
        for (int ks = 0; ks < 32; ks += 8) {
            unsigned af[4];
            af[0] = __float_as_uint(Ps[m0 + lr    ][ks + lc    ]);
            af[1] = __float_as_uint(Ps[m0 + lr + 8][ks + lc    ]);
            af[2] = __float_as_uint(Ps[m0 + lr    ][ks + lc + 4]);
            af[3] = __float_as_uint(Ps[m0 + lr + 8][ks + lc + 4]);
            unsigned bf[8][2];
            #pragma unroll
            for (int n = 0; n < 8; n++) {
                int c = wc + n*8 + lr;
                bf[n][0] = __float_as_uint(Whs[cur][ks + lc    ][c]);
                bf[n][1] = __float_as_uint(Whs[cur][ks + lc + 4][c]);
            }
            #pragma unroll
            for (int n = 0; n < 8; n++)
                mma_tf32(acc[n], af, bf[n]);
        }
        __syncthreads();
    }

    if (psub == 0) lS[prow] = l;
    __syncthreads();

    float* x3b = (float*)g_x3 + (size_t)b*NN*HD;
    #pragma unroll
    for (int half = 0; half < 2; half++) {
        int rloc = m0 + lr + half*8;
        float inv = 1.f / lS[rloc];
        float nmi = nmiS[rloc];
        size_t base = (size_t)(i0 + rloc)*HD;
        #pragma unroll
        for (int n = 0; n < 8; n++) {
            int col = wc + n*8 + 2*lc;
            float v0 = fmaxf(acc[n][half*2 + 0]*inv, 0.f) * nmi;
            float v1 = fmaxf(acc[n][half*2 + 1]*inv, 0.f) * nmi;
            *(float2*)&x3b[base + col] = make_float2(v0, v1);
        }
    }
}

// ============================================================================
// soft attention sigmoid
// ============================================================================
__global__ __launch_bounds__(256) void satt_kernel(const float* __restrict__ w_sa,
                                                   const float* __restrict__ b_sa) {
    int row  = blockIdx.x * 8 + (threadIdx.x >> 5);
    int lane = threadIdx.x & 31;
    float4 x = *(const float4*)&g_x3[(size_t)row*128 + lane*4];
    float4 w = *(const float4*)&w_sa[lane*4];
    float d = x.x*w.x + x.y*w.y + x.z*w.z + x.w*w.w;
    #pragma unroll
    for (int off = 16; off > 0; off >>= 1)
        d += __shfl_xor_sync(0xffffffffu, d, off);
    if (lane == 0) {
        float z = d + b_sa[0];
        g_satt[row] = 1.f / (1.f + __expf(-z));
    }
}

// ============================================================================
// Final layer (fp32 SIMT) + per-tile partial sum/max
// ============================================================================
__global__ __launch_bounds__(256) void final_gemm(const float* __restrict__ Wln,
                                                  const float* __restrict__ bln,
                                                  const float* __restrict__ mask) {
    __shared__ float As[64][32];
    __shared__ float Bs[32][128];
    __shared__ float redS[8][128];
    __shared__ float redM[8][128];
    const int r0 = blockIdx.x * 64;
    const int rg = threadIdx.x >> 5;
    const int cg = threadIdx.x & 31;
    float acc[8][4] = {};

    for (int k0 = 0; k0 < 128; k0 += 32) {
        #pragma unroll
        for (int i = threadIdx.x; i < 512; i += 256) {
            int r = i >> 3, q = i & 7;
            *(float4*)&As[r][q*4] = *(const float4*)&g_x3[(size_t)(r0 + r)*128 + k0 + q*4];
        }
        #pragma unroll
        for (int i = threadIdx.x; i < 1024; i += 256) {
            int r = i >> 5, q = i & 31;
            *(float4*)&Bs[r][q*4] = *(const float4*)&Wln[(k0 + r)*128 + q*4];
        }
        __syncthreads();
        #pragma unroll
        for (int kk = 0; kk < 32; kk++) {
            float4 bv = *(float4*)&Bs[kk][cg*4];
            #pragma unroll
            for (int r = 0; r < 8; r++) {
                float a = As[rg*8 + r][kk];
                acc[r][0] += a * bv.x; acc[r][1] += a * bv.y;
                acc[r][2] += a * bv.z; acc[r][3] += a * bv.w;
            }
        }
        __syncthreads();
    }

    float4 bl = *(const float4*)&bln[cg*4];
    float s[4]  = {0.f, 0.f, 0.f, 0.f};
    float mx[4] = {-INFINITY, -INFINITY, -INFINITY, -INFINITY};
    #pragma unroll
    for (int r = 0; r < 8; r++) {
        int row = r0 + rg*8 + r;
        float sa = g_satt[row] * mask[row];
        float v0 = fmaxf(acc[r][0] + bl.x, 0.f) * sa;
        float v1 = fmaxf(acc[r][1] + bl.y, 0.f) * sa;
        float v2 = fmaxf(acc[r][2] + bl.z, 0.f) * sa;
        float v3 = fmaxf(acc[r][3] + bl.w, 0.f) * sa;
        s[0] += v0; s[1] += v1; s[2] += v2; s[3] += v3;
        mx[0] = fmaxf(mx[0], v0); mx[1] = fmaxf(mx[1], v1);
        mx[2] = fmaxf(mx[2], v2); mx[3] = fmaxf(mx[3], v3);
    }
    #pragma unroll
    for (int c = 0; c < 4; c++) {
        redS[rg][cg*4 + c] = s[c];
        redM[rg][cg*4 + c] = mx[c];
    }
    __syncthreads();
    if (threadIdx.x < 32) {
        int bI = r0 >> 10;
        int t  = (r0 >> 6) & 15;
        #pragma unroll
        for (int c = 0; c < 4; c++) {
            int col = threadIdx.x*4 + c;
            float ss = 0.f, mm = -INFINITY;
            #pragma unroll
            for (int g = 0; g < 8; g++) {
                ss += redS[g][col];
                mm = fmaxf(mm, redM[g][col]);
            }
            g_psum[(bI*16 + t)*HD + col] = ss;
            g_pmax[(bI*16 + t)*HD + col] = mm;
        }
    }
}

__global__ void final_reduce(float* __restrict__ out) {
    int b = blockIdx.x, h = threadIdx.x;
    float s = 0.f, mx = -INFINITY;
    #pragma unroll
    for (int t = 0; t < 16; t++) {
        s += g_psum[(b*16 + t)*HD + h];
        mx = fmaxf(mx, g_pmax[(b*16 + t)*HD + h]);
    }
    out[b*HD + h] = s * mx;
}

// ============================================================================
extern "C" void kernel_launch(void* const* d_in, const int* in_sizes, int n_in,
                              void* d_out, int out_size) {
    const float* inputs = (const float*)d_in[0];
    const float* adj    = (const float*)d_in[1];
    const float* mask   = (const float*)d_in[2];
    const float* W0     = (const float*)d_in[3];
    const float* W1     = (const float*)d_in[4];
    const float* Wg     = (const float*)d_in[5];
    const float* a      = (const float*)d_in[6];
    const float* w_sa   = (const float*)d_in[7];
    const float* b_sa   = (const float*)d_in[8];
    const float* W_ln   = (const float*)d_in[9];
    const float* b_ln   = (const float*)d_in[10];
    float* out = (float*)d_out;

    cudaFuncSetAttribute(feat_gemm<0,0>, cudaFuncAttributeMaxDynamicSharedMemorySize, FEAT_SMEM_BYTES);
    cudaFuncSetAttribute(feat_gemm<1,0>, cudaFuncAttributeMaxDynamicSharedMemorySize, FEAT_SMEM_BYTES);
    cudaFuncSetAttribute(feat_gemm<2,1>, cudaFuncAttributeMaxDynamicSharedMemorySize, FEAT_SMEM_BYTES);
    cudaFuncSetAttribute(adj_gemm_f16<0>, cudaFuncAttributeMaxDynamicSharedMemorySize, ADJH_SMEM_BYTES);
    cudaFuncSetAttribute(adj_gemm_f16<1>, cudaFuncAttributeMaxDynamicSharedMemorySize, ADJH_SMEM_BYTES);
    cudaFuncSetAttribute(gat_tc, cudaFuncAttributeMaxDynamicSharedMemorySize, GATV1_SMEM_BYTES);

    const int ROWS = BB * NN;               // 16384
    dim3 gFeat(ROWS / 64);                  // 256
    dim3 gAdj(NN / 128, BB);                // (8,16)
    dim3 gGat(NN / 64, BB);                 // (16,16)
    dim3 gWarp(ROWS / 8);                   // 2048

    prep_adj<<<(BB*NN*NN)/(256*8), 256>>>(adj);

    // x1 = relu(adj @ (inputs @ W0)) * mask
    feat_gemm<0, 0><<<gFeat, 256, FEAT_SMEM_BYTES>>>(inputs, W0, nullptr);
    adj_gemm_f16<0><<<gAdj, 256, ADJH_SMEM_BYTES>>>(mask);
    // x2 = x1 + relu(adj @ (x1 @ W1)) * mask
    feat_gemm<1, 0><<<gFeat, 256, FEAT_SMEM_BYTES>>>(nullptr, W1, nullptr);
    adj_gemm_f16<1><<<gAdj, 256, ADJH_SMEM_BYTES>>>(mask);
    // GAT: Wh = x2 @ Wg (+ fused s1/s2)
    feat_gemm<2, 1><<<gFeat, 256, FEAT_SMEM_BYTES>>>(nullptr, Wg, a);
    gat_tc<<<gGat, 256, GATV1_SMEM_BYTES>>>(adj, mask);
    // epilogue
    satt_kernel<<<gWarp, 256>>>(w_sa, b_sa);
    final_gemm<<<gFeat, 256>>>(W_ln, b_ln, mask);
    final_reduce<<<BB, HD>>>(out);
}

// round 13
// speedup vs baseline: 1.1830x; 1.0003x over previous
#include <cuda_runtime.h>
#include <cuda_fp16.h>
#include <math.h>
#include <stdint.h>

#define BB 16
#define NN 1024
#define HD 128
#define NEGV (-9000000000000000.0f)
#define ALPHAV 0.2f

// ---------------- scratch (device globals; no allocation allowed) ----------------
__device__ __half g_adjh[(size_t)BB*NN*NN];   // fp16 adj (32 MB)
__device__ __half g_Yth[BB*HD*NN];            // fp16 (X@W)^T per batch [b][f][node]
__device__ float  g_X1[BB*NN*HD];
__device__ float  g_X2[BB*NN*HD];
__device__ float  g_Wh[BB*NN*HD];             // tf32-rounded (gat mma)
__device__ float  g_x3[BB*NN*HD];
__device__ float  g_s1[BB*NN];
__device__ float  g_s2[BB*NN];
__device__ float  g_satt[BB*NN];
__device__ float  g_psum[BB*16*HD];
__device__ float  g_pmax[BB*16*HD];

// ---------------- PTX helpers ----------------
__device__ __forceinline__ unsigned smem_u32(const void* p) {
    return (unsigned)__cvta_generic_to_shared(p);
}
__device__ __forceinline__ void cpa16(void* s, const void* g) {
    asm volatile("cp.async.cg.shared.global [%0], [%1], 16;" :: "r"(smem_u32(s)), "l"(g));
}
__device__ __forceinline__ void cpa_commit() { asm volatile("cp.async.commit_group;"); }
template<int N>
__device__ __forceinline__ void cpa_wait() { asm volatile("cp.async.wait_group %0;" :: "n"(N)); }
__device__ __forceinline__ unsigned f2tf(float f) {
    unsigned u; asm("cvt.rna.tf32.f32 %0, %1;" : "=r"(u) : "f"(f)); return u;
}
__device__ __forceinline__ void mma_tf32(float* c, const unsigned* a, const unsigned* b) {
    asm volatile(
        "mma.sync.aligned.m16n8k8.row.col.f32.tf32.tf32.f32 "
        "{%0,%1,%2,%3}, {%4,%5,%6,%7}, {%8,%9}, {%0,%1,%2,%3};"
        : "+f"(c[0]), "+f"(c[1]), "+f"(c[2]), "+f"(c[3])
        : "r"(a[0]), "r"(a[1]), "r"(a[2]), "r"(a[3]), "r"(b[0]), "r"(b[1]));
}
__device__ __forceinline__ void mma_f16(float* c, const unsigned* a, const unsigned* b) {
    asm volatile(
        "mma.sync.aligned.m16n8k16.row.col.f32.f16.f16.f32 "
        "{%0,%1,%2,%3}, {%4,%5,%6,%7}, {%8,%9}, {%0,%1,%2,%3};"
        : "+f"(c[0]), "+f"(c[1]), "+f"(c[2]), "+f"(c[3])
        : "r"(a[0]), "r"(a[1]), "r"(a[2]), "r"(a[3]), "r"(b[0]), "r"(b[1]));
}

// ============================================================================
// prep_adj: one-time fp32 -> fp16 (rna) copy of adj.
// ============================================================================
__global__ __launch_bounds__(256) void prep_adj(const float* __restrict__ adj) {
    size_t i = ((size_t)blockIdx.x * 256 + threadIdx.x) * 8;
    float4 v0 = *(const float4*)&adj[i];
    float4 v1 = *(const float4*)&adj[i + 4];
    __half2 h[4];
    h[0] = __floats2half2_rn(v0.x, v0.y);
    h[1] = __floats2half2_rn(v0.z, v0.w);
    h[2] = __floats2half2_rn(v1.x, v1.y);
    h[3] = __floats2half2_rn(v1.z, v1.w);
    *(uint4*)&g_adjh[i] = *(uint4*)h;
}

// ============================================================================
// Feature GEMM v2 (fp32 SIMT, identical FMA order to R11): C = X @ W.
// cp.async double-buffered, dynamic smem, 2 CTAs/SM.
// DST=0: fp16 transposed into g_Yth (Ts overlays pipeline buffers).
// DST=1: tf32-rounded fp32 into g_Wh + FUSED s1/s2 (bit-identical to s12_kernel).
// ============================================================================
#define FEAT_AS_BYTES (2*64*36*4)     // 18432
#define FEAT_BS_BYTES (2*32*136*4)    // 34816
#define FEAT_SMEM_BYTES (FEAT_AS_BYTES + FEAT_BS_BYTES)   // 53248

template<int SRC, int DST>
__global__ __launch_bounds__(256, 2) void feat_gemm(const float* __restrict__ Xext,
                                                    const float* __restrict__ W,
                                                    const float* __restrict__ avec) {
    extern __shared__ char dynsm[];
    float (*As)[64][36]  = reinterpret_cast<float(*)[64][36]>(dynsm);
    float (*Bs)[32][136] = reinterpret_cast<float(*)[32][136]>(dynsm + FEAT_AS_BYTES);

    const float* X = (SRC == 0) ? Xext : (SRC == 1) ? (const float*)g_X1 : (const float*)g_X2;

    const int tid = threadIdx.x;
    const int r0 = blockIdx.x * 64;
    const int rg = tid >> 5;
    const int cg = tid & 31;

    auto load_stage = [&](int st, int k0) {
        #pragma unroll
        for (int i = tid; i < 512; i += 256) {
            int r = i >> 3, q = i & 7;
            cpa16(&As[st][r][q*4], &X[(size_t)(r0 + r)*128 + k0 + q*4]);
        }
        #pragma unroll
        for (int i = tid; i < 1024; i += 256) {
            int r = i >> 5, q = i & 31;
            cpa16(&Bs[st][r][q*4], &W[(k0 + r)*128 + q*4]);
        }
        cpa_commit();
    };

    load_stage(0, 0);
    load_stage(1, 32);

    float acc[8][4] = {};

    #pragma unroll
    for (int kt = 0; kt < 4; kt++) {
        const int cur = kt & 1;
        if (kt < 3) cpa_wait<1>(); else cpa_wait<0>();
        __syncthreads();
        #pragma unroll
        for (int kk = 0; kk < 32; kk++) {
            float4 bv = *(float4*)&Bs[cur][kk][cg*4];
            #pragma unroll
            for (int r = 0; r < 8; r++) {
                float a = As[cur][rg*8 + r][kk];
                acc[r][0] += a * bv.x; acc[r][1] += a * bv.y;
                acc[r][2] += a * bv.z; acc[r][3] += a * bv.w;
            }
        }
        __syncthreads();
        if (kt + 2 < 4) load_stage(cur, (kt + 2) * 32);
    }

    if constexpr (DST == 0) {
        // fp16 transpose epilogue: Ts overlays the As/Bs region (compute done)
        __half (*Ts)[136] = reinterpret_cast<__half(*)[136]>(dynsm);
        #pragma unroll
        for (int r = 0; r < 8; r++) {
            Ts[rg*8 + r][cg*4 + 0] = __float2half_rn(acc[r][0]);
            Ts[rg*8 + r][cg*4 + 1] = __float2half_rn(acc[r][1]);
            Ts[rg*8 + r][cg*4 + 2] = __float2half_rn(acc[r][2]);
            Ts[rg*8 + r][cg*4 + 3] = __float2half_rn(acc[r][3]);
        }
        __syncthreads();
        int b  = r0 >> 10;
        int k0 = r0 & 1023;
        int f  = tid >> 1;
        int kh = (tid & 1) * 32;
        __half* dst = (__half*)g_Yth + ((size_t)b*HD + f)*NN + k0 + kh;
        #pragma unroll
        for (int q = 0; q < 32; q += 2) {
            __half2 hv = __halves2half2(Ts[kh + q][f], Ts[kh + q + 1][f]);
            *(__half2*)&dst[q] = hv;
        }
    } else {
        // tf32-round, store Wh, and fuse s1/s2 (same expression + reduce order
        // as the old s12_kernel on the same rounded values -> bit-identical)
        float rr[8][4];
        #pragma unroll
        for (int r = 0; r < 8; r++) {
            rr[r][0] = __uint_as_float(f2tf(acc[r][0]));
            rr[r][1] = __uint_as_float(f2tf(acc[r][1]));
            rr[r][2] = __uint_as_float(f2tf(acc[r][2]));
            rr[r][3] = __uint_as_float(f2tf(acc[r][3]));
            *(float4*)&g_Wh[(size_t)(r0 + rg*8 + r)*128 + cg*4] =
                make_float4(rr[r][0], rr[r][1], rr[r][2], rr[r][3]);
        }
        float4 a1 = *(const float4*)&avec[cg*4];
        float4 a2 = *(const float4*)&avec[128 + cg*4];
        #pragma unroll
        for (int r = 0; r < 8; r++) {
            float d1 = rr[r][0]*a1.x + rr[r][1]*a1.y + rr[r][2]*a1.z + rr[r][3]*a1.w;
            float d2 = rr[r][0]*a2.x + rr[r][1]*a2.y + rr[r][2]*a2.z + rr[r][3]*a2.w;
            #pragma unroll
            for (int off = 16; off > 0; off >>= 1) {
                d1 += __shfl_xor_sync(0xffffffffu, d1, off);
                d2 += __shfl_xor_sync(0xffffffffu, d2, off);
            }
            if (cg == 0) {
                int row = r0 + rg*8 + r;
                g_s1[row] = d1;
                g_s2[row] = d2;
            }
        }
    }
}

// ============================================================================
// Adjacency GEMM fp16 (R11 verbatim): CTA 128x128, BK=64, 16 k-tiles,
// 8 warps 4m x 2n, 3-stage cp.async.
// ============================================================================
#define ADJH_TILE_BYTES (128*72*2)
#define ADJH_STAGE_BYTES (2*ADJH_TILE_BYTES)
#define ADJH_SMEM_BYTES (3*ADJH_STAGE_BYTES)             // 110592

template<int MODE>
__global__ __launch_bounds__(256, 1) void adj_gemm_f16(const float* __restrict__ mask) {
    extern __shared__ char dynsm[];
    __half (*As)[128][72] = reinterpret_cast<__half(*)[128][72]>(dynsm);
    __half (*Bs)[128][72] = reinterpret_cast<__half(*)[128][72]>(dynsm + 3*ADJH_TILE_BYTES);

    const int b  = blockIdx.y;
    const int r0 = blockIdx.x * 128;
    const __half* A  = (const __half*)g_adjh + (size_t)b*NN*NN;
    const __half* Bt = (const __half*)g_Yth  + (size_t)b*HD*NN;
    const int tid = threadIdx.x;

    auto load_stage = [&](int st, int k0) {
        #pragma unroll
        for (int i = tid; i < 1024; i += 256) {
            int r = i >> 3, q = i & 7;
            cpa16(&As[st][r][q*8], &A[(size_t)(r0 + r)*NN + k0 + q*8]);
        }
        #pragma unroll
        for (int i = tid; i < 1024; i += 256) {
            int f = i >> 3, q = i & 7;
            cpa16(&Bs[st][f][q*8], &Bt[(size_t)f*NN + k0 + q*8]);
        }
        cpa_commit();
    };

    load_stage(0, 0);
    load_stage(1, 64);

    const int warp = tid >> 5, lane = tid & 31;
    const int wr = (warp >> 1) * 32;
    const int wc = (warp & 1) * 64;
    const int lr = lane >> 2;
    const int lc = lane & 3;

    float acc[2][8][4];
    #pragma unroll
    for (int mt = 0; mt < 2; mt++)
        #pragma unroll
        for (int n = 0; n < 8; n++)
            #pragma unroll
            for (int q = 0; q < 4; q++) acc[mt][n][q] = 0.f;

    for (int kt = 0; kt < 16; kt++) {
        const int cur = kt % 3;
        cpa_wait<1>();
        __syncthreads();

        #pragma unroll
        for (int s = 0; s < 4; s++) {
            const int kb = s * 16;
            unsigned af[2][4];
            #pragma unroll
            for (int mt = 0; mt < 2; mt++) {
                int r = wr + mt*16 + lr;
                af[mt][0] = *(const unsigned*)&As[cur][r    ][kb + 2*lc    ];
                af[mt][1] = *(const unsigned*)&As[cur][r + 8][kb + 2*lc    ];
                af[mt][2] = *(const unsigned*)&As[cur][r    ][kb + 2*lc + 8];
                af[mt][3] = *(const unsigned*)&As[cur][r + 8][kb + 2*lc + 8];
            }
            unsigned bf[8][2];
            #pragma unroll
            for (int n = 0; n < 8; n++) {
                int c = wc + n*8 + lr;
                bf[n][0] = *(const unsigned*)&Bs[cur][c][kb + 2*lc    ];
                bf[n][1] = *(const unsigned*)&Bs[cur][c][kb + 2*lc + 8];
            }
            #pragma unroll
            for (int mt = 0; mt < 2; mt++)
                #pragma unroll
                for (int n = 0; n < 8; n++)
                    mma_f16(acc[mt][n], af[mt], bf[n]);
        }

        if (kt + 2 < 16) load_stage((kt + 2) % 3, (kt + 2) * 64);
    }

    #pragma unroll
    for (int mt = 0; mt < 2; mt++) {
        #pragma unroll
        for (int half = 0; half < 2; half++) {
            int row = r0 + wr + mt*16 + lr + half*8;
            float mk = mask[b*NN + row];
            size_t base = (size_t)b*NN*HD + (size_t)row*HD;
            #pragma unroll
            for (int n = 0; n < 8; n++) {
                int col = wc + n*8 + 2*lc;
                float v0 = fmaxf(acc[mt][n][half*2 + 0], 0.f) * mk;
                float v1 = fmaxf(acc[mt][n][half*2 + 1], 0.f) * mk;
                if (MODE == 1) {
                    float2 x = *(const float2*)&g_X1[base + col];
                    v0 += x.x; v1 += x.y;
                    *(float2*)&g_X2[base + col] = make_float2(v0, v1);
                } else {
                    *(float2*)&g_X1[base + col] = make_float2(v0, v1);
                }
            }
        }
    }
}

// ============================================================================
// GAT (R9/R11 verbatim): 64 query rows/CTA, j-tiles of 32, online softmax
// 4 threads/row x 8 cols, P@Wh tf32 warp tile 16x64, 2 CTAs/SM.
// ============================================================================
#define GATV1_WHS_BYTES (2*32*136*4)
#define GATV1_PS_BYTES  (64*36*4)
#define GATV1_SMEM_BYTES (GATV1_WHS_BYTES + GATV1_PS_BYTES + 4*64*4)   // 45056

__global__ __launch_bounds__(256, 2) void gat_tc(const float* __restrict__ adj,
                                                 const float* __restrict__ mask) {
    extern __shared__ char dynsm[];
    float (*Whs)[32][136] = reinterpret_cast<float(*)[32][136]>(dynsm);
    float (*Ps)[36]       = reinterpret_cast<float(*)[36]>(dynsm + GATV1_WHS_BYTES);
    float* scaleS = reinterpret_cast<float*>(dynsm + GATV1_WHS_BYTES + GATV1_PS_BYTES);
    float* lS     = scaleS + 64;
    float* s1S    = scaleS + 128;
    float* nmiS   = scaleS + 192;

    const int b  = blockIdx.y;
    const int i0 = blockIdx.x * 64;
    const float* Ab  = adj + (size_t)b*NN*NN;
    const float* Whb = (const float*)g_Wh + (size_t)b*NN*HD;

    const int tid  = threadIdx.x;
    const int warp = tid >> 5, lane = tid & 31;
    const int m0   = (warp >> 1) * 16;
    const int wc   = (warp & 1) * 64;
    const int lr   = lane >> 2, lc = lane & 3;
    const int prow = tid >> 2, psub = tid & 3;

    if (tid < 64) {
        s1S[tid]  = g_s1[b*NN + i0 + tid];
        nmiS[tid] = mask[b*NN + i0 + tid];
    }

    auto load_wh = [&](int st, int j0) {
        #pragma unroll
        for (int i = tid; i < 1024; i += 256) {
            int r = i >> 5, q = i & 31;
            cpa16(&Whs[st][r][q*4], &Whb[(size_t)(j0 + r)*HD + q*4]);
        }
        cpa_commit();
    };

    load_wh(0, 0);

    const float* arow_base = Ab + (size_t)(i0 + prow)*NN + psub*8;
    float4 pa0 = *(const float4*)&arow_base[0];
    float4 pa1 = *(const float4*)&arow_base[4];

    float acc[8][4];
    #pragma unroll
    for (int n = 0; n < 8; n++)
        #pragma unroll
        for (int q = 0; q < 4; q++) acc[n][q] = 0.f;

    float m = -INFINITY, l = 0.f;
    __syncthreads();

    for (int jt = 0; jt < 32; jt++) {
        const int cur = jt & 1;
        const int j0  = jt * 32;
        if (jt + 1 < 32) load_wh(cur ^ 1, j0 + 32);

        float s1v = s1S[prow], nmi = nmiS[prow];
        float4 s2a = *(const float4*)&g_s2[b*NN + j0 + psub*8];
        float4 s2b = *(const float4*)&g_s2[b*NN + j0 + psub*8 + 4];
        float4 nma = *(const float4*)&mask[b*NN + j0 + psub*8];
        float4 nmb = *(const float4*)&mask[b*NN + j0 + psub*8 + 4];
        float s2v[8] = {s2a.x, s2a.y, s2a.z, s2a.w, s2b.x, s2b.y, s2b.z, s2b.w};
        float nmv[8] = {nma.x, nma.y, nma.z, nma.w, nmb.x, nmb.y, nmb.z, nmb.w};
        float av[8]  = {pa0.x, pa0.y, pa0.z, pa0.w, pa1.x, pa1.y, pa1.z, pa1.w};

        float vals[8];
        float tmax = -INFINITY;
        #pragma unroll
        for (int jj = 0; jj < 8; jj++) {
            float e = s1v + s2v[jj];
            e = (e > 0.f) ? e : ALPHAV * e;
            float edge = (av[jj] > 0.f) ? (nmv[jj] * nmi) : 0.f;
            float v = (edge > 0.f) ? e : NEGV;
            vals[jj] = v;
            tmax = fmaxf(tmax, v);
        }
        tmax = fmaxf(tmax, __shfl_xor_sync(0xffffffffu, tmax, 1));
        tmax = fmaxf(tmax, __shfl_xor_sync(0xffffffffu, tmax, 2));
        float mn    = fmaxf(m, tmax);
        float scale = __expf(m - mn);
        float psum = 0.f;
        #pragma unroll
        for (int jj = 0; jj < 8; jj++) {
            float p = __expf(vals[jj] - mn);
            float pr = __uint_as_float(f2tf(p));   // rounded once; in BOTH l and P@Wh
            Ps[prow][psub*8 + jj] = pr;
            psum += pr;
        }
        psum += __shfl_xor_sync(0xffffffffu, psum, 1);
        psum += __shfl_xor_sync(0xffffffffu, psum, 2);
        l = l * scale + psum;
        m = mn;
        if (psub == 0) scaleS[prow] = scale;

        if (jt + 1 < 32) {
            pa0 = *(const float4*)&arow_base[j0 + 32];
            pa1 = *(const float4*)&arow_base[j0 + 36];
        }

        if (jt + 1 < 32) cpa_wait<1>(); else cpa_wait<0>();
        __syncthreads();

        float sc0 = scaleS[m0 + lr], sc1 = scaleS[m0 + lr + 8];
        #pragma unroll
        for (int n = 0; n < 8; n++) {
            acc[n][0] *= sc0; acc[n][1] *= sc0;
            acc[n][2] *= sc1; acc[n][3] *= sc1;
        }
        #pragma unroll
        for (int ks = 0; ks < 32; ks += 8) {
            unsigned af[4];
            af[0] = __float_as_uint(Ps[m0 + lr    ][ks + lc    ]);
            af[1] = __float_as_uint(Ps[m0 + lr + 8][ks + lc    ]);
            af[2] = __float_as_uint(Ps[m0 + lr    ][ks + lc + 4]);
            af[3] = __float_as_uint(Ps[m0 + lr + 8][ks + lc + 4]);
            unsigned bf[8][2];
            #pragma unroll
            for (int n = 0; n < 8; n++) {
                int c = wc + n*8 + lr;
                bf[n][0] = __float_as_uint(Whs[cur][ks + lc    ][c]);
                bf[n][1] = __float_as_uint(Whs[cur][ks + lc + 4][c]);
            }
            #pragma unroll
            for (int n = 0; n < 8; n++)
                mma_tf32(acc[n], af, bf[n]);
        }
        __syncthreads();
    }

    if (psub == 0) lS[prow] = l;
    __syncthreads();

    float* x3b = (float*)g_x3 + (size_t)b*NN*HD;
    #pragma unroll
    for (int half = 0; half < 2; half++) {
        int rloc = m0 + lr + half*8;
        float inv = 1.f / lS[rloc];
        float nmi = nmiS[rloc];
        size_t base = (size_t)(i0 + rloc)*HD;
        #pragma unroll
        for (int n = 0; n < 8; n++) {
            int col = wc + n*8 + 2*lc;
            float v0 = fmaxf(acc[n][half*2 + 0]*inv, 0.f) * nmi;
            float v1 = fmaxf(acc[n][half*2 + 1]*inv, 0.f) * nmi;
            *(float2*)&x3b[base + col] = make_float2(v0, v1);
        }
    }
}

// ============================================================================
// soft attention sigmoid
// ============================================================================
__global__ __launch_bounds__(256) void satt_kernel(const float* __restrict__ w_sa,
                                                   const float* __restrict__ b_sa) {
    int row  = blockIdx.x * 8 + (threadIdx.x >> 5);
    int lane = threadIdx.x & 31;
    float4 x = *(const float4*)&g_x3[(size_t)row*128 + lane*4];
    float4 w = *(const float4*)&w_sa[lane*4];
    float d = x.x*w.x + x.y*w.y + x.z*w.z + x.w*w.w;
    #pragma unroll
    for (int off = 16; off > 0; off >>= 1)
        d += __shfl_xor_sync(0xffffffffu, d, off);
    if (lane == 0) {
        float z = d + b_sa[0];
        g_satt[row] = 1.f / (1.f + __expf(-z));
    }
}

// ============================================================================
// Final layer (fp32 SIMT) + per-tile partial sum/max
// ============================================================================
__global__ __launch_bounds__(256) void final_gemm(const float* __restrict__ Wln,
                                                  const float* __restrict__ bln,
                                                  const float* __restrict__ mask) {
    __shared__ float As[64][32];
    __shared__ float Bs[32][128];
    __shared__ float redS[8][128];
    __shared__ float redM[8][128];
    const int r0 = blockIdx.x * 64;
    const int rg = threadIdx.x >> 5;
    const int cg = threadIdx.x & 31;
    float acc[8][4] = {};

    for (int k0 = 0; k0 < 128; k0 += 32) {
        #pragma unroll
        for (int i = threadIdx.x; i < 512; i += 256) {
            int r = i >> 3, q = i & 7;
            *(float4*)&As[r][q*4] = *(const float4*)&g_x3[(size_t)(r0 + r)*128 + k0 + q*4];
        }
        #pragma unroll
        for (int i = threadIdx.x; i < 1024; i += 256) {
            int r = i >> 5, q = i & 31;
            *(float4*)&Bs[r][q*4] = *(const float4*)&Wln[(k0 + r)*128 + q*4];
        }
        __syncthreads();
        #pragma unroll
        for (int kk = 0; kk < 32; kk++) {
            float4 bv = *(float4*)&Bs[kk][cg*4];
            #pragma unroll
            for (int r = 0; r < 8; r++) {
                float a = As[rg*8 + r][kk];
                acc[r][0] += a * bv.x; acc[r][1] += a * bv.y;
                acc[r][2] += a * bv.z; acc[r][3] += a * bv.w;
            }
        }
        __syncthreads();
    }

    float4 bl = *(const float4*)&bln[cg*4];
    float s[4]  = {0.f, 0.f, 0.f, 0.f};
    float mx[4] = {-INFINITY, -INFINITY, -INFINITY, -INFINITY};
    #pragma unroll
    for (int r = 0; r < 8; r++) {
        int row = r0 + rg*8 + r;
        float sa = g_satt[row] * mask[row];
        float v0 = fmaxf(acc[r][0] + bl.x, 0.f) * sa;
        float v1 = fmaxf(acc[r][1] + bl.y, 0.f) * sa;
        float v2 = fmaxf(acc[r][2] + bl.z, 0.f) * sa;
        float v3 = fmaxf(acc[r][3] + bl.w, 0.f) * sa;
        s[0] += v0; s[1] += v1; s[2] += v2; s[3] += v3;
        mx[0] = fmaxf(mx[0], v0); mx[1] = fmaxf(mx[1], v1);
        mx[2] = fmaxf(mx[2], v2); mx[3] = fmaxf(mx[3], v3);
    }
    #pragma unroll
    for (int c = 0; c < 4; c++) {
        redS[rg][cg*4 + c] = s[c];
        redM[rg][cg*4 + c] = mx[c];
    }
    __syncthreads();
    if (threadIdx.x < 32) {
        int bI = r0 >> 10;
        int t  = (r0 >> 6) & 15;
        #pragma unroll
        for (int c = 0; c < 4; c++) {
            int col = threadIdx.x*4 + c;
            float ss = 0.f, mm = -INFINITY;
            #pragma unroll
            for (int g = 0; g < 8; g++) {
                ss += redS[g][col];
                mm = fmaxf(mm, redM[g][col]);
            }
            g_psum[(bI*16 + t)*HD + col] = ss;
            g_pmax[(bI*16 + t)*HD + col] = mm;
        }
    }
}

__global__ void final_reduce(float* __restrict__ out) {
    int b = blockIdx.x, h = threadIdx.x;
    float s = 0.f, mx = -INFINITY;
    #pragma unroll
    for (int t = 0; t < 16; t++) {
        s += g_psum[(b*16 + t)*HD + h];
        mx = fmaxf(mx, g_pmax[(b*16 + t)*HD + h]);
    }
    out[b*HD + h] = s * mx;
}

// ============================================================================
extern "C" void kernel_launch(void* const* d_in, const int* in_sizes, int n_in,
                              void* d_out, int out_size) {
    const float* inputs = (const float*)d_in[0];
    const float* adj    = (const float*)d_in[1];
    const float* mask   = (const float*)d_in[2];
    const float* W0     = (const float*)d_in[3];
    const float* W1     = (const float*)d_in[4];
    const float* Wg     = (const float*)d_in[5];
    const float* a      = (const float*)d_in[6];
    const float* w_sa   = (const float*)d_in[7];
    const float* b_sa   = (const float*)d_in[8];
    const float* W_ln   = (const float*)d_in[9];
    const float* b_ln   = (const float*)d_in[10];
    float* out = (float*)d_out;

    cudaFuncSetAttribute(feat_gemm<0,0>, cudaFuncAttributeMaxDynamicSharedMemorySize, FEAT_SMEM_BYTES);
    cudaFuncSetAttribute(feat_gemm<1,0>, cudaFuncAttributeMaxDynamicSharedMemorySize, FEAT_SMEM_BYTES);
    cudaFuncSetAttribute(feat_gemm<2,1>, cudaFuncAttributeMaxDynamicSharedMemorySize, FEAT_SMEM_BYTES);
    cudaFuncSetAttribute(adj_gemm_f16<0>, cudaFuncAttributeMaxDynamicSharedMemorySize, ADJH_SMEM_BYTES);
    cudaFuncSetAttribute(adj_gemm_f16<1>, cudaFuncAttributeMaxDynamicSharedMemorySize, ADJH_SMEM_BYTES);
    cudaFuncSetAttribute(gat_tc, cudaFuncAttributeMaxDynamicSharedMemorySize, GATV1_SMEM_BYTES);

    const int ROWS = BB * NN;               // 16384
    dim3 gFeat(ROWS / 64);                  // 256
    dim3 gAdj(NN / 128, BB);                // (8,16)
    dim3 gGat(NN / 64, BB);                 // (16,16)
    dim3 gWarp(ROWS / 8);                   // 2048

    prep_adj<<<(BB*NN*NN)/(256*8), 256>>>(adj);

    // x1 = relu(adj @ (inputs @ W0)) * mask
    feat_gemm<0, 0><<<gFeat, 256, FEAT_SMEM_BYTES>>>(inputs, W0, nullptr);
    adj_gemm_f16<0><<<gAdj, 256, ADJH_SMEM_BYTES>>>(mask);
    // x2 = x1 + relu(adj @ (x1 @ W1)) * mask
    feat_gemm<1, 0><<<gFeat, 256, FEAT_SMEM_BYTES>>>(nullptr, W1, nullptr);
    adj_gemm_f16<1><<<gAdj, 256, ADJH_SMEM_BYTES>>>(mask);
    // GAT: Wh = x2 @ Wg (+ fused s1/s2)
    feat_gemm<2, 1><<<gFeat, 256, FEAT_SMEM_BYTES>>>(nullptr, Wg, a);
    gat_tc<<<gGat, 256, GATV1_SMEM_BYTES>>>(adj, mask);
    // epilogue
    satt_kernel<<<gWarp, 256>>>(w_sa, b_sa);
    final_gemm<<<gFeat, 256>>>(W_ln, b_ln, mask);
    final_reduce<<<BB, HD>>>(out);
}

// round 14
// speedup vs baseline: 1.1944x; 1.0096x over previous
#include <cuda_runtime.h>
#include <cuda_fp16.h>
#include <math.h>
#include <stdint.h>

#define BB 16
#define NN 1024
#define HD 128
#define NEGV (-9000000000000000.0f)
#define ALPHAV 0.2f

// ---------------- scratch (device globals; no allocation allowed) ----------------
__device__ __half g_adjh[(size_t)BB*NN*NN];   // fp16 adj (32 MB)
__device__ __half g_Yth[BB*HD*NN];            // fp16 (X@W)^T per batch [b][f][node]
__device__ float  g_X1[BB*NN*HD];
__device__ float  g_X2[BB*NN*HD];
__device__ float  g_Wh[BB*NN*HD];             // tf32-rounded (gat mma)
__device__ float  g_x3[BB*NN*HD];
__device__ float  g_s1[BB*NN];
__device__ float  g_s2[BB*NN];
__device__ float  g_satt[BB*NN];
__device__ float  g_psum[BB*16*HD];
__device__ float  g_pmax[BB*16*HD];

// ---------------- PTX helpers ----------------
__device__ __forceinline__ unsigned smem_u32(const void* p) {
    return (unsigned)__cvta_generic_to_shared(p);
}
__device__ __forceinline__ void cpa16(void* s, const void* g) {
    asm volatile("cp.async.cg.shared.global [%0], [%1], 16;" :: "r"(smem_u32(s)), "l"(g));
}
__device__ __forceinline__ void cpa_commit() { asm volatile("cp.async.commit_group;"); }
template<int N>
__device__ __forceinline__ void cpa_wait() { asm volatile("cp.async.wait_group %0;" :: "n"(N)); }
__device__ __forceinline__ unsigned f2tf(float f) {
    unsigned u; asm("cvt.rna.tf32.f32 %0, %1;" : "=r"(u) : "f"(f)); return u;
}
__device__ __forceinline__ void mma_tf32(float* c, const unsigned* a, const unsigned* b) {
    asm volatile(
        "mma.sync.aligned.m16n8k8.row.col.f32.tf32.tf32.f32 "
        "{%0,%1,%2,%3}, {%4,%5,%6,%7}, {%8,%9}, {%0,%1,%2,%3};"
        : "+f"(c[0]), "+f"(c[1]), "+f"(c[2]), "+f"(c[3])
        : "r"(a[0]), "r"(a[1]), "r"(a[2]), "r"(a[3]), "r"(b[0]), "r"(b[1]));
}
__device__ __forceinline__ void mma_f16(float* c, const unsigned* a, const unsigned* b) {
    asm volatile(
        "mma.sync.aligned.m16n8k16.row.col.f32.f16.f16.f32 "
        "{%0,%1,%2,%3}, {%4,%5,%6,%7}, {%8,%9}, {%0,%1,%2,%3};"
        : "+f"(c[0]), "+f"(c[1]), "+f"(c[2]), "+f"(c[3])
        : "r"(a[0]), "r"(a[1]), "r"(a[2]), "r"(a[3]), "r"(b[0]), "r"(b[1]));
}

// ============================================================================
// prep_adj: one-time fp32 -> fp16 (rna) copy of adj.
// ============================================================================
__global__ __launch_bounds__(256) void prep_adj(const float* __restrict__ adj) {
    size_t i = ((size_t)blockIdx.x * 256 + threadIdx.x) * 8;
    float4 v0 = *(const float4*)&adj[i];
    float4 v1 = *(const float4*)&adj[i + 4];
    __half2 h[4];
    h[0] = __floats2half2_rn(v0.x, v0.y);
    h[1] = __floats2half2_rn(v0.z, v0.w);
    h[2] = __floats2half2_rn(v1.x, v1.y);
    h[3] = __floats2half2_rn(v1.z, v1.w);
    *(uint4*)&g_adjh[i] = *(uint4*)h;
}

// ============================================================================
// Feature GEMM v2 (fp32 SIMT, identical FMA order to R11): C = X @ W.
// cp.async double-buffered, dynamic smem, 2 CTAs/SM.
// DST=0: fp16 transposed into g_Yth (Ts overlays pipeline buffers).
// DST=1: tf32-rounded fp32 into g_Wh + FUSED s1/s2 (bit-identical to s12_kernel).
// ============================================================================
#define FEAT_AS_BYTES (2*64*36*4)     // 18432
#define FEAT_BS_BYTES (2*32*136*4)    // 34816
#define FEAT_SMEM_BYTES (FEAT_AS_BYTES + FEAT_BS_BYTES)   // 53248

template<int SRC, int DST>
__global__ __launch_bounds__(256, 2) void feat_gemm(const float* __restrict__ Xext,
                                                    const float* __restrict__ W,
                                                    const float* __restrict__ avec) {
    extern __shared__ char dynsm[];
    float (*As)[64][36]  = reinterpret_cast<float(*)[64][36]>(dynsm);
    float (*Bs)[32][136] = reinterpret_cast<float(*)[32][136]>(dynsm + FEAT_AS_BYTES);

    const float* X = (SRC == 0) ? Xext : (SRC == 1) ? (const float*)g_X1 : (const float*)g_X2;

    const int tid = threadIdx.x;
    const int r0 = blockIdx.x * 64;
    const int rg = tid >> 5;
    const int cg = tid & 31;

    auto load_stage = [&](int st, int k0) {
        #pragma unroll
        for (int i = tid; i < 512; i += 256) {
            int r = i >> 3, q = i & 7;
            cpa16(&As[st][r][q*4], &X[(size_t)(r0 + r)*128 + k0 + q*4]);
        }
        #pragma unroll
        for (int i = tid; i < 1024; i += 256) {
            int r = i >> 5, q = i & 31;
            cpa16(&Bs[st][r][q*4], &W[(k0 + r)*128 + q*4]);
        }
        cpa_commit();
    };

    load_stage(0, 0);
    load_stage(1, 32);

    float acc[8][4] = {};

    #pragma unroll
    for (int kt = 0; kt < 4; kt++) {
        const int cur = kt & 1;
        if (kt < 3) cpa_wait<1>(); else cpa_wait<0>();
        __syncthreads();
        #pragma unroll
        for (int kk = 0; kk < 32; kk++) {
            float4 bv = *(float4*)&Bs[cur][kk][cg*4];
            #pragma unroll
            for (int r = 0; r < 8; r++) {
                float a = As[cur][rg*8 + r][kk];
                acc[r][0] += a * bv.x; acc[r][1] += a * bv.y;
                acc[r][2] += a * bv.z; acc[r][3] += a * bv.w;
            }
        }
        __syncthreads();
        if (kt + 2 < 4) load_stage(cur, (kt + 2) * 32);
    }

    if constexpr (DST == 0) {
        // fp16 transpose epilogue: Ts overlays the As/Bs region (compute done)
        __half (*Ts)[136] = reinterpret_cast<__half(*)[136]>(dynsm);
        #pragma unroll
        for (int r = 0; r < 8; r++) {
            Ts[rg*8 + r][cg*4 + 0] = __float2half_rn(acc[r][0]);
            Ts[rg*8 + r][cg*4 + 1] = __float2half_rn(acc[r][1]);
            Ts[rg*8 + r][cg*4 + 2] = __float2half_rn(acc[r][2]);
            Ts[rg*8 + r][cg*4 + 3] = __float2half_rn(acc[r][3]);
        }
        __syncthreads();
        int b  = r0 >> 10;
        int k0 = r0 & 1023;
        int f  = tid >> 1;
        int kh = (tid & 1) * 32;
        __half* dst = (__half*)g_Yth + ((size_t)b*HD + f)*NN + k0 + kh;
        #pragma unroll
        for (int q = 0; q < 32; q += 2) {
            __half2 hv = __halves2half2(Ts[kh + q][f], Ts[kh + q + 1][f]);
            *(__half2*)&dst[q] = hv;
        }
    } else {
        // tf32-round, store Wh, and fuse s1/s2 (same expression + reduce order
        // as the old s12_kernel on the same rounded values -> bit-identical)
        float rr[8][4];
        #pragma unroll
        for (int r = 0; r < 8; r++) {
            rr[r][0] = __uint_as_float(f2tf(acc[r][0]));
            rr[r][1] = __uint_as_float(f2tf(acc[r][1]));
            rr[r][2] = __uint_as_float(f2tf(acc[r][2]));
            rr[r][3] = __uint_as_float(f2tf(acc[r][3]));
            *(float4*)&g_Wh[(size_t)(r0 + rg*8 + r)*128 + cg*4] =
                make_float4(rr[r][0], rr[r][1], rr[r][2], rr[r][3]);
        }
        float4 a1 = *(const float4*)&avec[cg*4];
        float4 a2 = *(const float4*)&avec[128 + cg*4];
        #pragma unroll
        for (int r = 0; r < 8; r++) {
            float d1 = rr[r][0]*a1.x + rr[r][1]*a1.y + rr[r][2]*a1.z + rr[r][3]*a1.w;
            float d2 = rr[r][0]*a2.x + rr[r][1]*a2.y + rr[r][2]*a2.z + rr[r][3]*a2.w;
            #pragma unroll
            for (int off = 16; off > 0; off >>= 1) {
                d1 += __shfl_xor_sync(0xffffffffu, d1, off);
                d2 += __shfl_xor_sync(0xffffffffu, d2, off);
            }
            if (cg == 0) {
                int row = r0 + rg*8 + r;
                g_s1[row] = d1;
                g_s2[row] = d2;
            }
        }
    }
}

// ============================================================================
// Adjacency GEMM fp16 (R11 verbatim): CTA 128x128, BK=64, 16 k-tiles,
// 8 warps 4m x 2n, 3-stage cp.async.
// ============================================================================
#define ADJH_TILE_BYTES (128*72*2)
#define ADJH_STAGE_BYTES (2*ADJH_TILE_BYTES)
#define ADJH_SMEM_BYTES (3*ADJH_STAGE_BYTES)             // 110592

template<int MODE>
__global__ __launch_bounds__(256, 1) void adj_gemm_f16(const float* __restrict__ mask) {
    extern __shared__ char dynsm[];
    __half (*As)[128][72] = reinterpret_cast<__half(*)[128][72]>(dynsm);
    __half (*Bs)[128][72] = reinterpret_cast<__half(*)[128][72]>(dynsm + 3*ADJH_TILE_BYTES);

    const int b  = blockIdx.y;
    const int r0 = blockIdx.x * 128;
    const __half* A  = (const __half*)g_adjh + (size_t)b*NN*NN;
    const __half* Bt = (const __half*)g_Yth  + (size_t)b*HD*NN;
    const int tid = threadIdx.x;

    auto load_stage = [&](int st, int k0) {
        #pragma unroll
        for (int i = tid; i < 1024; i += 256) {
            int r = i >> 3, q = i & 7;
            cpa16(&As[st][r][q*8], &A[(size_t)(r0 + r)*NN + k0 + q*8]);
        }
        #pragma unroll
        for (int i = tid; i < 1024; i += 256) {
            int f = i >> 3, q = i & 7;
            cpa16(&Bs[st][f][q*8], &Bt[(size_t)f*NN + k0 + q*8]);
        }
        cpa_commit();
    };

    load_stage(0, 0);
    load_stage(1, 64);

    const int warp = tid >> 5, lane = tid & 31;
    const int wr = (warp >> 1) * 32;
    const int wc = (warp & 1) * 64;
    const int lr = lane >> 2;
    const int lc = lane & 3;

    float acc[2][8][4];
    #pragma unroll
    for (int mt = 0; mt < 2; mt++)
        #pragma unroll
        for (int n = 0; n < 8; n++)
            #pragma unroll
            for (int q = 0; q < 4; q++) acc[mt][n][q] = 0.f;

    for (int kt = 0; kt < 16; kt++) {
        const int cur = kt % 3;
        cpa_wait<1>();
        __syncthreads();

        #pragma unroll
        for (int s = 0; s < 4; s++) {
            const int kb = s * 16;
            unsigned af[2][4];
            #pragma unroll
            for (int mt = 0; mt < 2; mt++) {
                int r = wr + mt*16 + lr;
                af[mt][0] = *(const unsigned*)&As[cur][r    ][kb + 2*lc    ];
                af[mt][1] = *(const unsigned*)&As[cur][r + 8][kb + 2*lc    ];
                af[mt][2] = *(const unsigned*)&As[cur][r    ][kb + 2*lc + 8];
                af[mt][3] = *(const unsigned*)&As[cur][r + 8][kb + 2*lc + 8];
            }
            unsigned bf[8][2];
            #pragma unroll
            for (int n = 0; n < 8; n++) {
                int c = wc + n*8 + lr;
                bf[n][0] = *(const unsigned*)&Bs[cur][c][kb + 2*lc    ];
                bf[n][1] = *(const unsigned*)&Bs[cur][c][kb + 2*lc + 8];
            }
            #pragma unroll
            for (int mt = 0; mt < 2; mt++)
                #pragma unroll
                for (int n = 0; n < 8; n++)
                    mma_f16(acc[mt][n], af[mt], bf[n]);
        }

        if (kt + 2 < 16) load_stage((kt + 2) % 3, (kt + 2) * 64);
    }

    #pragma unroll
    for (int mt = 0; mt < 2; mt++) {
        #pragma unroll
        for (int half = 0; half < 2; half++) {
            int row = r0 + wr + mt*16 + lr + half*8;
            float mk = mask[b*NN + row];
            size_t base = (size_t)b*NN*HD + (size_t)row*HD;
            #pragma unroll
            for (int n = 0; n < 8; n++) {
                int col = wc + n*8 + 2*lc;
                float v0 = fmaxf(acc[mt][n][half*2 + 0], 0.f) * mk;
                float v1 = fmaxf(acc[mt][n][half*2 + 1], 0.f) * mk;
                if (MODE == 1) {
                    float2 x = *(const float2*)&g_X1[base + col];
                    v0 += x.x; v1 += x.y;
                    *(float2*)&g_X2[base + col] = make_float2(v0, v1);
                } else {
                    *(float2*)&g_X1[base + col] = make_float2(v0, v1);
                }
            }
        }
    }
}

// ============================================================================
// GAT (R9/R11 verbatim): 64 query rows/CTA, j-tiles of 32, online softmax
// 4 threads/row x 8 cols, P@Wh tf32 warp tile 16x64, 2 CTAs/SM.
// ============================================================================
#define GATV1_WHS_BYTES (2*32*136*4)
#define GATV1_PS_BYTES  (64*36*4)
#define GATV1_SMEM_BYTES (GATV1_WHS_BYTES + GATV1_PS_BYTES + 4*64*4)   // 45056

__global__ __launch_bounds__(256, 2) void gat_tc(const float* __restrict__ adj,
                                                 const float* __restrict__ mask) {
    extern __shared__ char dynsm[];
    float (*Whs)[32][136] = reinterpret_cast<float(*)[32][136]>(dynsm);
    float (*Ps)[36]       = reinterpret_cast<float(*)[36]>(dynsm + GATV1_WHS_BYTES);
    float* scaleS = reinterpret_cast<float*>(dynsm + GATV1_WHS_BYTES + GATV1_PS_BYTES);
    float* lS     = scaleS + 64;
    float* s1S    = scaleS + 128;
    float* nmiS   = scaleS + 192;

    const int b  = blockIdx.y;
    const int i0 = blockIdx.x * 64;
    const float* Ab  = adj + (size_t)b*NN*NN;
    const float* Whb = (const float*)g_Wh + (size_t)b*NN*HD;

    const int tid  = threadIdx.x;
    const int warp = tid >> 5, lane = tid & 31;
    const int m0   = (warp >> 1) * 16;
    const int wc   = (warp & 1) * 64;
    const int lr   = lane >> 2, lc = lane & 3;
    const int prow = tid >> 2, psub = tid & 3;

    if (tid < 64) {
        s1S[tid]  = g_s1[b*NN + i0 + tid];
        nmiS[tid] = mask[b*NN + i0 + tid];
    }

    auto load_wh = [&](int st, int j0) {
        #pragma unroll
        for (int i = tid; i < 1024; i += 256) {
            int r = i >> 5, q = i & 31;
            cpa16(&Whs[st][r][q*4], &Whb[(size_t)(j0 + r)*HD + q*4]);
        }
        cpa_commit();
    };

    load_wh(0, 0);

    const float* arow_base = Ab + (size_t)(i0 + prow)*NN + psub*8;
    float4 pa0 = *(const float4*)&arow_base[0];
    float4 pa1 = *(const float4*)&arow_base[4];

    float acc[8][4];
    #pragma unroll
    for (int n = 0; n < 8; n++)
        #pragma unroll
        for (int q = 0; q < 4; q++) acc[n][q] = 0.f;

    float m = -INFINITY, l = 0.f;
    __syncthreads();

    for (int jt = 0; jt < 32; jt++) {
        const int cur = jt & 1;
        const int j0  = jt * 32;
        if (jt + 1 < 32) load_wh(cur ^ 1, j0 + 32);

        float s1v = s1S[prow], nmi = nmiS[prow];
        float4 s2a = *(const float4*)&g_s2[b*NN + j0 + psub*8];
        float4 s2b = *(const float4*)&g_s2[b*NN + j0 + psub*8 + 4];
        float4 nma = *(const float4*)&mask[b*NN + j0 + psub*8];
        float4 nmb = *(const float4*)&mask[b*NN + j0 + psub*8 + 4];
        float s2v[8] = {s2a.x, s2a.y, s2a.z, s2a.w, s2b.x, s2b.y, s2b.z, s2b.w};
        float nmv[8] = {nma.x, nma.y, nma.z, nma.w, nmb.x, nmb.y, nmb.z, nmb.w};
        float av[8]  = {pa0.x, pa0.y, pa0.z, pa0.w, pa1.x, pa1.y, pa1.z, pa1.w};

        float vals[8];
        float tmax = -INFINITY;
        #pragma unroll
        for (int jj = 0; jj < 8; jj++) {
            float e = s1v + s2v[jj];
            e = (e > 0.f) ? e : ALPHAV * e;
            float edge = (av[jj] > 0.f) ? (nmv[jj] * nmi) : 0.f;
            float v = (edge > 0.f) ? e : NEGV;
            vals[jj] = v;
            tmax = fmaxf(tmax, v);
        }
        tmax = fmaxf(tmax, __shfl_xor_sync(0xffffffffu, tmax, 1));
        tmax = fmaxf(tmax, __shfl_xor_sync(0xffffffffu, tmax, 2));
        float mn    = fmaxf(m, tmax);
        float scale = __expf(m - mn);
        float psum = 0.f;
        #pragma unroll
        for (int jj = 0; jj < 8; jj++) {
            float p = __expf(vals[jj] - mn);
            float pr = __uint_as_float(f2tf(p));   // rounded once; in BOTH l and P@Wh
            Ps[prow][psub*8 + jj] = pr;
            psum += pr;
        }
        psum += __shfl_xor_sync(0xffffffffu, psum, 1);
        psum += __shfl_xor_sync(0xffffffffu, psum, 2);
        l = l * scale + psum;
        m = mn;
        if (psub == 0) scaleS[prow] = scale;

        if (jt + 1 < 32) {
            pa0 = *(const float4*)&arow_base[j0 + 32];
            pa1 = *(const float4*)&arow_base[j0 + 36];
        }

        if (jt + 1 < 32) cpa_wait<1>(); else cpa_wait<0>();
        __syncthreads();

        float sc0 = scaleS[m0 + lr], sc1 = scaleS[m0 + lr + 8];
        #pragma unroll
        for (int n = 0; n < 8; n++) {
            acc[n][0] *= sc0; acc[n][1] *= sc0;
            acc[n][2] *= sc1; acc[n][3] *= sc1;
        }
        #pragma unroll
        for (int ks = 0; ks < 32; ks += 8) {
            unsigned af[4];
            af[0] = __float_as_uint(Ps[m0 + lr    ][ks + lc    ]);
            af[1] = __float_as_uint(Ps[m0 + lr + 8][ks + lc    ]);
            af[2] = __float_as_uint(Ps[m0 + lr    ][ks + lc + 4]);
            af[3] = __float_as_uint(Ps[m0 + lr + 8][ks + lc + 4]);
            unsigned bf[8][2];
            #pragma unroll
            for (int n = 0; n < 8; n++) {
                int c = wc + n*8 + lr;
                bf[n][0] = __float_as_uint(Whs[cur][ks + lc    ][c]);
                bf[n][1] = __float_as_uint(Whs[cur][ks + lc + 4][c]);
            }
            #pragma unroll
            for (int n = 0; n < 8; n++)
                mma_tf32(acc[n], af, bf[n]);
        }
        __syncthreads();
    }

    if (psub == 0) lS[prow] = l;
    __syncthreads();

    float* x3b = (float*)g_x3 + (size_t)b*NN*HD;
    #pragma unroll
    for (int half = 0; half < 2; half++) {
        int rloc = m0 + lr + half*8;
        float inv = 1.f / lS[rloc];
        float nmi = nmiS[rloc];
        size_t base = (size_t)(i0 + rloc)*HD;
        #pragma unroll
        for (int n = 0; n < 8; n++) {
            int col = wc + n*8 + 2*lc;
            float v0 = fmaxf(acc[n][half*2 + 0]*inv, 0.f) * nmi;
            float v1 = fmaxf(acc[n][half*2 + 1]*inv, 0.f) * nmi;
            *(float2*)&x3b[base + col] = make_float2(v0, v1);
        }
    }
}

// ============================================================================
// soft attention sigmoid
// ============================================================================
__global__ __launch_bounds__(256) void satt_kernel(const float* __restrict__ w_sa,
                                                   const float* __restrict__ b_sa) {
    int row  = blockIdx.x * 8 + (threadIdx.x >> 5);
    int lane = threadIdx.x & 31;
    float4 x = *(const float4*)&g_x3[(size_t)row*128 + lane*4];
    float4 w = *(const float4*)&w_sa[lane*4];
    float d = x.x*w.x + x.y*w.y + x.z*w.z + x.w*w.w;
    #pragma unroll
    for (int off = 16; off > 0; off >>= 1)
        d += __shfl_xor_sync(0xffffffffu, d, off);
    if (lane == 0) {
        float z = d + b_sa[0];
        g_satt[row] = 1.f / (1.f + __expf(-z));
    }
}

// ============================================================================
// Final layer (fp32 SIMT) + per-tile partial sum/max
// ============================================================================
__global__ __launch_bounds__(256) void final_gemm(const float* __restrict__ Wln,
                                                  const float* __restrict__ bln,
                                                  const float* __restrict__ mask) {
    __shared__ float As[64][32];
    __shared__ float Bs[32][128];
    __shared__ float redS[8][128];
    __shared__ float redM[8][128];
    const int r0 = blockIdx.x * 64;
    const int rg = threadIdx.x >> 5;
    const int cg = threadIdx.x & 31;
    float acc[8][4] = {};

    for (int k0 = 0; k0 < 128; k0 += 32) {
        #pragma unroll
        for (int i = threadIdx.x; i < 512; i += 256) {
            int r = i >> 3, q = i & 7;
            *(float4*)&As[r][q*4] = *(const float4*)&g_x3[(size_t)(r0 + r)*128 + k0 + q*4];
        }
        #pragma unroll
        for (int i = threadIdx.x; i < 1024; i += 256) {
            int r = i >> 5, q = i & 31;
            *(float4*)&Bs[r][q*4] = *(const float4*)&Wln[(k0 + r)*128 + q*4];
        }
        __syncthreads();
        #pragma unroll
        for (int kk = 0; kk < 32; kk++) {
            float4 bv = *(float4*)&Bs[kk][cg*4];
            #pragma unroll
            for (int r = 0; r < 8; r++) {
                float a = As[rg*8 + r][kk];
                acc[r][0] += a * bv.x; acc[r][1] += a * bv.y;
                acc[r][2] += a * bv.z; acc[r][3] += a * bv.w;
            }
        }
        __syncthreads();
    }

    float4 bl = *(const float4*)&bln[cg*4];
    float s[4]  = {0.f, 0.f, 0.f, 0.f};
    float mx[4] = {-INFINITY, -INFINITY, -INFINITY, -INFINITY};
    #pragma unroll
    for (int r = 0; r < 8; r++) {
        int row = r0 + rg*8 + r;
        float sa = g_satt[row] * mask[row];
        float v0 = fmaxf(acc[r][0] + bl.x, 0.f) * sa;
        float v1 = fmaxf(acc[r][1] + bl.y, 0.f) * sa;
        float v2 = fmaxf(acc[r][2] + bl.z, 0.f) * sa;
        float v3 = fmaxf(acc[r][3] + bl.w, 0.f) * sa;
        s[0] += v0; s[1] += v1; s[2] += v2; s[3] += v3;
        mx[0] = fmaxf(mx[0], v0); mx[1] = fmaxf(mx[1], v1);
        mx[2] = fmaxf(mx[2], v2); mx[3] = fmaxf(mx[3], v3);
    }
    #pragma unroll
    for (int c = 0; c < 4; c++) {
        redS[rg][cg*4 + c] = s[c];
        redM[rg][cg*4 + c] = mx[c];
    }
    __syncthreads();
    if (threadIdx.x < 32) {
        int bI = r0 >> 10;
        int t  = (r0 >> 6) & 15;
        #pragma unroll
        for (int c = 0; c < 4; c++) {
            int col = threadIdx.x*4 + c;
            float ss = 0.f, mm = -INFINITY;
            #pragma unroll
            for (int g = 0; g < 8; g++) {
                ss += redS[g][col];
                mm = fmaxf(mm, redM[g][col]);
            }
            g_psum[(bI*16 + t)*HD + col] = ss;
            g_pmax[(bI*16 + t)*HD + col] = mm;
        }
    }
}

__global__ void final_reduce(float* __restrict__ out) {
    int b = blockIdx.x, h = threadIdx.x;
    float s = 0.f, mx = -INFINITY;
    #pragma unroll
    for (int t = 0; t < 16; t++) {
        s += g_psum[(b*16 + t)*HD + h];
        mx = fmaxf(mx, g_pmax[(b*16 + t)*HD + h]);
    }
    out[b*HD + h] = s * mx;
}

// ============================================================================
extern "C" void kernel_launch(void* const* d_in, const int* in_sizes, int n_in,
                              void* d_out, int out_size) {
    const float* inputs = (const float*)d_in[0];
    const float* adj    = (const float*)d_in[1];
    const float* mask   = (const float*)d_in[2];
    const float* W0     = (const float*)d_in[3];
    const float* W1     = (const float*)d_in[4];
    const float* Wg     = (const float*)d_in[5];
    const float* a      = (const float*)d_in[6];
    const float* w_sa   = (const float*)d_in[7];
    const float* b_sa   = (const float*)d_in[8];
    const float* W_ln   = (const float*)d_in[9];
    const float* b_ln   = (const float*)d_in[10];
    float* out = (float*)d_out;

    cudaFuncSetAttribute(feat_gemm<0,0>, cudaFuncAttributeMaxDynamicSharedMemorySize, FEAT_SMEM_BYTES);
    cudaFuncSetAttribute(feat_gemm<1,0>, cudaFuncAttributeMaxDynamicSharedMemorySize, FEAT_SMEM_BYTES);
    cudaFuncSetAttribute(feat_gemm<2,1>, cudaFuncAttributeMaxDynamicSharedMemorySize, FEAT_SMEM_BYTES);
    cudaFuncSetAttribute(adj_gemm_f16<0>, cudaFuncAttributeMaxDynamicSharedMemorySize, ADJH_SMEM_BYTES);
    cudaFuncSetAttribute(adj_gemm_f16<1>, cudaFuncAttributeMaxDynamicSharedMemorySize, ADJH_SMEM_BYTES);
    cudaFuncSetAttribute(gat_tc, cudaFuncAttributeMaxDynamicSharedMemorySize, GATV1_SMEM_BYTES);

    const int ROWS = BB * NN;               // 16384
    dim3 gFeat(ROWS / 64);                  // 256
    dim3 gAdj(NN / 128, BB);                // (8,16)
    dim3 gGat(NN / 64, BB);                 // (16,16)
    dim3 gWarp(ROWS / 8);                   // 2048

    prep_adj<<<(BB*NN*NN)/(256*8), 256>>>(adj);

    // x1 = relu(adj @ (inputs @ W0)) * mask
    feat_gemm<0, 0><<<gFeat, 256, FEAT_SMEM_BYTES>>>(inputs, W0, nullptr);
    adj_gemm_f16<0><<<gAdj, 256, ADJH_SMEM_BYTES>>>(mask);
    // x2 = x1 + relu(adj @ (x1 @ W1)) * mask
    feat_gemm<1, 0><<<gFeat, 256, FEAT_SMEM_BYTES>>>(nullptr, W1, nullptr);
    adj_gemm_f16<1><<<gAdj, 256, ADJH_SMEM_BYTES>>>(mask);
    // GAT: Wh = x2 @ Wg (+ fused s1/s2)
    feat_gemm<2, 1><<<gFeat, 256, FEAT_SMEM_BYTES>>>(nullptr, Wg, a);
    gat_tc<<<gGat, 256, GATV1_SMEM_BYTES>>>(adj, mask);
    // epilogue
    satt_kernel<<<gWarp, 256>>>(w_sa, b_sa);
    final_gemm<<<gFeat, 256>>>(W_ln, b_ln, mask);
    final_reduce<<<BB, HD>>>(out);
}